// round 10
// baseline (speedup 1.0000x reference)
#include <cuda_runtime.h>
#include <cuda_bf16.h>
#include <cstdint>
#include <math.h>

#define Bq 2
#define Lq 2048
#define Dq 1024
#define Hq 16
#define HDq 64
#define HALFW 128
#define QT 128

// Scratch (no cudaMalloc allowed)
__device__ __nv_bfloat16 g_qkvh[(size_t)Bq * Lq * 3 * Dq];  // [B,L,3,D] hi plane
__device__ __nv_bfloat16 g_qkvl[(size_t)Bq * Lq * 3 * Dq];  // lo plane
__device__ __nv_bfloat16 g_x_hi[(size_t)Bq * Lq * Dq];
__device__ __nv_bfloat16 g_x_lo[(size_t)Bq * Lq * Dq];
__device__ __nv_bfloat16 g_wqkv_hi[(size_t)Dq * 3 * Dq];
__device__ __nv_bfloat16 g_wqkv_lo[(size_t)Dq * 3 * Dq];
__device__ __nv_bfloat16 g_wout_hi[(size_t)Dq * Dq];
__device__ __nv_bfloat16 g_wout_lo[(size_t)Dq * Dq];
__device__ __nv_bfloat16 g_attn_hi[(size_t)Bq * Lq * Dq];
__device__ __nv_bfloat16 g_attn_lo[(size_t)Bq * Lq * Dq];

// ===========================================================================
// helpers
// ===========================================================================
__device__ __forceinline__ void bf16_split(float x, uint16_t& hi, uint16_t& lo) {
    __nv_bfloat16 h = __float2bfloat16(x);
    float hf = __bfloat162float(h);
    __nv_bfloat16 l = __float2bfloat16(x - hf);
    hi = __nv_bfloat16_raw(h).x;
    lo = __nv_bfloat16_raw(l).x;
}

__device__ __forceinline__ uint32_t pack2(uint16_t a, uint16_t b) {
    return (uint32_t)a | ((uint32_t)b << 16);
}

__device__ __forceinline__ uint32_t smem_u32(const void* p) {
    uint32_t a;
    asm("{ .reg .u64 t; cvta.to.shared.u64 t, %1; cvt.u32.u64 %0, t; }" : "=r"(a) : "l"(p));
    return a;
}

__device__ __forceinline__ void ldm_x4(uint32_t& r0, uint32_t& r1, uint32_t& r2, uint32_t& r3,
                                       uint32_t addr) {
    asm volatile("ldmatrix.sync.aligned.m8n8.x4.shared.b16 {%0,%1,%2,%3}, [%4];"
                 : "=r"(r0), "=r"(r1), "=r"(r2), "=r"(r3) : "r"(addr));
}
__device__ __forceinline__ void ldm_x4_t(uint32_t& r0, uint32_t& r1, uint32_t& r2, uint32_t& r3,
                                         uint32_t addr) {
    asm volatile("ldmatrix.sync.aligned.m8n8.x4.trans.shared.b16 {%0,%1,%2,%3}, [%4];"
                 : "=r"(r0), "=r"(r1), "=r"(r2), "=r"(r3) : "r"(addr));
}

__device__ __forceinline__ void mma_bf16(float& d0, float& d1, float& d2, float& d3,
                                         uint32_t a0, uint32_t a1, uint32_t a2, uint32_t a3,
                                         uint32_t b0, uint32_t b1) {
    asm volatile(
        "mma.sync.aligned.m16n8k16.row.col.f32.bf16.bf16.f32 "
        "{%0,%1,%2,%3}, {%4,%5,%6,%7}, {%8,%9}, {%0,%1,%2,%3};"
        : "+f"(d0), "+f"(d1), "+f"(d2), "+f"(d3)
        : "r"(a0), "r"(a1), "r"(a2), "r"(a3), "r"(b0), "r"(b1));
}

// ===========================================================================
// split kernel: fp32 -> bf16 hi + lo
// ===========================================================================
__global__ void __launch_bounds__(256)
split_bf16(const float* __restrict__ in, __nv_bfloat16* __restrict__ hi,
           __nv_bfloat16* __restrict__ lo, int n)
{
    int i = (blockIdx.x * 256 + threadIdx.x) * 4;
    if (i >= n) return;
    float4 v = *(const float4*)(in + i);
    uint16_t h0, l0, h1, l1, h2, l2, h3, l3;
    bf16_split(v.x, h0, l0);
    bf16_split(v.y, h1, l1);
    bf16_split(v.z, h2, l2);
    bf16_split(v.w, h3, l3);
    *(uint2*)(hi + i) = make_uint2(pack2(h0, h1), pack2(h2, h3));
    *(uint2*)(lo + i) = make_uint2(pack2(l0, l1), pack2(l2, l3));
}

// ===========================================================================
// bf16x3 GEMM, pre-split operands, 512 threads (16 warps, 4/SMSP).
// CTA tile 128x128, warp tile 32x32 (4x4 warps), K-chunk 32, double buffered.
// Dedicated A-lo fragment regs; all 8 ldmatrix hoisted before each 24-mma burst.
// ===========================================================================
#define A_STRIDE 40
#define B_STRIDE 136
#define A_PLANE  (128 * A_STRIDE * 2)
#define B_PLANE  (32 * B_STRIDE * 2)
#define OFF_AHI  0
#define OFF_ALO  (A_PLANE)
#define OFF_BHI  (2 * A_PLANE)
#define OFF_BLO  (2 * A_PLANE + B_PLANE)
#define BUF_BYTES (2 * A_PLANE + 2 * B_PLANE)
#define SMEM_GEMM_BYTES (2 * BUF_BYTES)

template<bool SPLIT_OUT>
__global__ void __launch_bounds__(512, 1)
gemm_bf16x3_pre(const __nv_bfloat16* __restrict__ Ahi, const __nv_bfloat16* __restrict__ Alo,
                const __nv_bfloat16* __restrict__ Bhi, const __nv_bfloat16* __restrict__ Blo,
                const float* __restrict__ bias, float* __restrict__ C,
                __nv_bfloat16* __restrict__ Chi, __nv_bfloat16* __restrict__ Clo,
                int M, int N, int K)
{
    extern __shared__ char smem[];
    const uint32_t sbase = smem_u32(smem);
    const int t    = threadIdx.x;
    const int lane = t & 31;
    const int wid  = t >> 5;
    const int warp_m = wid >> 2;      // 0..3
    const int warp_n = wid & 3;       // 0..3

    const int n0 = blockIdx.x * 128;
    const int m0 = blockIdx.y * 128;

    float acc[2][4][4];
#pragma unroll
    for (int i = 0; i < 2; i++)
#pragma unroll
        for (int j = 0; j < 4; j++)
#pragma unroll
            for (int r = 0; r < 4; r++) acc[i][j][r] = 0.f;

    // loaders: one uint4 per plane per thread
    const int a_m = t >> 2, a_g = t & 3;     // A: 128 rows x 4 col-groups(8)
    const int b_k = t >> 4, b_ng = t & 15;   // B: 32 rows x 16 col-groups(8)

    uint4 pah, pal, pbh, pbl;
    pah = *(const uint4*)(Ahi + (size_t)(m0 + a_m) * K + a_g * 8);
    pal = *(const uint4*)(Alo + (size_t)(m0 + a_m) * K + a_g * 8);
    pbh = *(const uint4*)(Bhi + (size_t)b_k * N + n0 + b_ng * 8);
    pbl = *(const uint4*)(Blo + (size_t)b_k * N + n0 + b_ng * 8);

    const int NCH = K / 32;
    for (int c = 0; c < NCH; c++) {
        const uint32_t buf = sbase + (c & 1) * BUF_BYTES;

        // store chunk to smem
        {
            uint32_t aaddr = buf + OFF_AHI + a_m * (A_STRIDE * 2) + a_g * 16;
            asm volatile("st.shared.v4.b32 [%0], {%1,%2,%3,%4};" ::
                "r"(aaddr), "r"(pah.x), "r"(pah.y), "r"(pah.z), "r"(pah.w) : "memory");
            asm volatile("st.shared.v4.b32 [%0], {%1,%2,%3,%4};" ::
                "r"(aaddr + (OFF_ALO - OFF_AHI)),
                "r"(pal.x), "r"(pal.y), "r"(pal.z), "r"(pal.w) : "memory");
            uint32_t baddr = buf + OFF_BHI + b_k * (B_STRIDE * 2) + b_ng * 16;
            asm volatile("st.shared.v4.b32 [%0], {%1,%2,%3,%4};" ::
                "r"(baddr), "r"(pbh.x), "r"(pbh.y), "r"(pbh.z), "r"(pbh.w) : "memory");
            asm volatile("st.shared.v4.b32 [%0], {%1,%2,%3,%4};" ::
                "r"(baddr + (OFF_BLO - OFF_BHI)),
                "r"(pbl.x), "r"(pbl.y), "r"(pbl.z), "r"(pbl.w) : "memory");
        }
        __syncthreads();

        // prefetch next chunk (gmem latency hidden under mma)
        if (c + 1 < NCH) {
            int k0n = (c + 1) * 32;
            pah = *(const uint4*)(Ahi + (size_t)(m0 + a_m) * K + k0n + a_g * 8);
            pal = *(const uint4*)(Alo + (size_t)(m0 + a_m) * K + k0n + a_g * 8);
            pbh = *(const uint4*)(Bhi + (size_t)(k0n + b_k) * N + n0 + b_ng * 8);
            pbl = *(const uint4*)(Blo + (size_t)(k0n + b_k) * N + n0 + b_ng * 8);
        }

        // mma: 2 k16 steps x (hh + hl + lh), all frags loaded up front
#pragma unroll
        for (int kk = 0; kk < 2; kk++) {
            const int a_row = (lane & 15);
            const int a_cb  = (lane >> 4);
            const int b_kr  = kk * 16 + (lane & 15);
            const int b_nc  = (lane & 16) ? 8 : 0;

            uint32_t ah[2][4], al[2][4], bh[2][4], bl[2][4];
#pragma unroll
            for (int mt = 0; mt < 2; mt++) {
                int row = warp_m * 32 + mt * 16 + a_row;
                uint32_t ad = buf + OFF_AHI + (row * A_STRIDE + kk * 16 + a_cb * 8) * 2;
                ldm_x4(ah[mt][0], ah[mt][1], ah[mt][2], ah[mt][3], ad);
                ldm_x4(al[mt][0], al[mt][1], al[mt][2], al[mt][3], ad + (OFF_ALO - OFF_AHI));
            }
#pragma unroll
            for (int nb = 0; nb < 2; nb++) {
                int ncol = warp_n * 32 + nb * 16 + b_nc;
                uint32_t bd = buf + OFF_BHI + (b_kr * B_STRIDE + ncol) * 2;
                ldm_x4_t(bh[nb][0], bh[nb][1], bh[nb][2], bh[nb][3], bd);
                ldm_x4_t(bl[nb][0], bl[nb][1], bl[nb][2], bl[nb][3], bd + (OFF_BLO - OFF_BHI));
            }
#pragma unroll
            for (int mt = 0; mt < 2; mt++)
#pragma unroll
                for (int nt = 0; nt < 4; nt++) {
                    int nb = nt >> 1, half = nt & 1;
                    mma_bf16(acc[mt][nt][0], acc[mt][nt][1], acc[mt][nt][2], acc[mt][nt][3],
                             ah[mt][0], ah[mt][1], ah[mt][2], ah[mt][3],
                             bh[nb][half * 2], bh[nb][half * 2 + 1]);
                    mma_bf16(acc[mt][nt][0], acc[mt][nt][1], acc[mt][nt][2], acc[mt][nt][3],
                             ah[mt][0], ah[mt][1], ah[mt][2], ah[mt][3],
                             bl[nb][half * 2], bl[nb][half * 2 + 1]);
                }
#pragma unroll
            for (int mt = 0; mt < 2; mt++)
#pragma unroll
                for (int nt = 0; nt < 4; nt++) {
                    int nb = nt >> 1, half = nt & 1;
                    mma_bf16(acc[mt][nt][0], acc[mt][nt][1], acc[mt][nt][2], acc[mt][nt][3],
                             al[mt][0], al[mt][1], al[mt][2], al[mt][3],
                             bh[nb][half * 2], bh[nb][half * 2 + 1]);
                }
        }
        // no trailing sync — double buffer + program order makes it safe
    }

    const int r_base = m0 + warp_m * 32 + (lane >> 2);
    const int c_base = n0 + warp_n * 32 + 2 * (lane & 3);
#pragma unroll
    for (int mt = 0; mt < 2; mt++) {
#pragma unroll
        for (int nt = 0; nt < 4; nt++) {
            int col = c_base + nt * 8;
            float b0 = bias[col], b1 = bias[col + 1];
            int r0 = r_base + mt * 16;
            float v00 = acc[mt][nt][0] + b0, v01 = acc[mt][nt][1] + b1;
            float v10 = acc[mt][nt][2] + b0, v11 = acc[mt][nt][3] + b1;
            if (SPLIT_OUT) {
                uint16_t h0, l0, h1, l1;
                bf16_split(v00, h0, l0); bf16_split(v01, h1, l1);
                *(uint32_t*)(Chi + (size_t)r0 * N + col) = pack2(h0, h1);
                *(uint32_t*)(Clo + (size_t)r0 * N + col) = pack2(l0, l1);
                bf16_split(v10, h0, l0); bf16_split(v11, h1, l1);
                *(uint32_t*)(Chi + (size_t)(r0 + 8) * N + col) = pack2(h0, h1);
                *(uint32_t*)(Clo + (size_t)(r0 + 8) * N + col) = pack2(l0, l1);
            } else {
                *(float2*)(C + (size_t)r0 * N + col)       = make_float2(v00, v01);
                *(float2*)(C + (size_t)(r0 + 8) * N + col) = make_float2(v10, v11);
            }
        }
    }
}

// ===========================================================================
// Tensor-core windowed flash attention (unchanged from round 9 — passing)
// ===========================================================================
#define AT_STR 144
#define OFF_KH 0
#define OFF_KL 18432
#define OFF_VH 36864
#define OFF_VL 55296
#define SMEM_ATT 73728

__global__ void __launch_bounds__(256, 1)
attn_flash(const __nv_bfloat16* __restrict__ qh_g, const __nv_bfloat16* __restrict__ ql_g,
           __nv_bfloat16* __restrict__ ohi, __nv_bfloat16* __restrict__ olo)
{
    extern __shared__ char smem[];
    const uint32_t sb = smem_u32(smem);
    const int qt = blockIdx.x, h = blockIdx.y, b = blockIdx.z;
    const int t = threadIdx.x, lane = t & 31, wid = t >> 5;

#pragma unroll
    for (int p = 0; p < 8; p++) {
        int idx = t + p * 256;
        int pl = idx >> 10, rem = idx & 1023, row = rem >> 3, g = rem & 7;
        const __nv_bfloat16* src = (pl ? ql_g : qh_g)
            + ((size_t)(b * Lq + qt * QT + row) * 3 + 0) * Dq + h * HDq + g * 8;
        uint4 v = *(const uint4*)src;
        uint32_t dst = sb + (pl ? OFF_KL : OFF_KH) + row * AT_STR + g * 16;
        asm volatile("st.shared.v4.b32 [%0], {%1,%2,%3,%4};" ::
                     "r"(dst), "r"(v.x), "r"(v.y), "r"(v.z), "r"(v.w) : "memory");
    }
    __syncthreads();

    uint32_t qfh[4][4], qfl[4][4];
    {
        int a_row = lane & 15, a_cb = lane >> 4;
        int qrow = wid * 16 + a_row;
#pragma unroll
        for (int ks = 0; ks < 4; ks++) {
            uint32_t ad = sb + OFF_KH + qrow * AT_STR + (ks * 16 + a_cb * 8) * 2;
            ldm_x4(qfh[ks][0], qfh[ks][1], qfh[ks][2], qfh[ks][3], ad);
            ldm_x4(qfl[ks][0], qfl[ks][1], qfl[ks][2], qfl[ks][3], ad + (OFF_KL - OFF_KH));
        }
    }

    float o[8][4];
#pragma unroll
    for (int i = 0; i < 8; i++)
#pragma unroll
        for (int r = 0; r < 4; r++) o[i][r] = 0.f;
    float ls0 = 0.f, ls1 = 0.f;

    const int i_lo = wid * 16 + (lane >> 2);
    const int i_hi = i_lo + 8;
    const int jj_b = (lane & 3) * 2;

    const int bn_row = (lane & 7) + ((lane & 16) >> 1);
    const int bk_off = (lane & 8);
    const int v_kr = (lane & 15);
    const int v_nc = (lane & 16) ? 8 : 0;

    for (int ch = 0; ch < 3; ch++) {
        if (ch == 0 && qt == 0) continue;
        if (ch == 2 && qt == (Lq / QT) - 1) continue;
        const int jbase = qt * QT + (ch - 1) * 128;

        __syncthreads();
#pragma unroll
        for (int p = 0; p < 16; p++) {
            int idx = t + p * 256;
            int plane = idx >> 10, rem = idx & 1023, row = rem >> 3, g = rem & 7;
            int which = (plane < 2) ? 1 : 2;
            const __nv_bfloat16* src = ((plane & 1) ? ql_g : qh_g)
                + ((size_t)(b * Lq + jbase + row) * 3 + which) * Dq + h * HDq + g * 8;
            uint4 v = *(const uint4*)src;
            uint32_t off = (plane == 0) ? OFF_KH : (plane == 1) ? OFF_KL
                         : (plane == 2) ? OFF_VH : OFF_VL;
            uint32_t dst = sb + off + row * AT_STR + g * 16;
            asm volatile("st.shared.v4.b32 [%0], {%1,%2,%3,%4};" ::
                         "r"(dst), "r"(v.x), "r"(v.y), "r"(v.z), "r"(v.w) : "memory");
        }
        __syncthreads();

        float sacc[16][4];
#pragma unroll
        for (int i = 0; i < 16; i++)
#pragma unroll
            for (int r = 0; r < 4; r++) sacc[i][r] = 0.f;

#pragma unroll
        for (int ks = 0; ks < 4; ks++) {
#pragma unroll
            for (int ng = 0; ng < 8; ng++) {
                uint32_t kh0, kh1, kh2, kh3, kl0, kl1, kl2, kl3;
                uint32_t ad = sb + OFF_KH + (ng * 16 + bn_row) * AT_STR + (ks * 16 + bk_off) * 2;
                ldm_x4(kh0, kh1, kh2, kh3, ad);
                ldm_x4(kl0, kl1, kl2, kl3, ad + (OFF_KL - OFF_KH));
                int n0 = ng * 2, n1 = ng * 2 + 1;
                mma_bf16(sacc[n0][0], sacc[n0][1], sacc[n0][2], sacc[n0][3],
                         qfh[ks][0], qfh[ks][1], qfh[ks][2], qfh[ks][3], kh0, kh1);
                mma_bf16(sacc[n1][0], sacc[n1][1], sacc[n1][2], sacc[n1][3],
                         qfh[ks][0], qfh[ks][1], qfh[ks][2], qfh[ks][3], kh2, kh3);
                mma_bf16(sacc[n0][0], sacc[n0][1], sacc[n0][2], sacc[n0][3],
                         qfh[ks][0], qfh[ks][1], qfh[ks][2], qfh[ks][3], kl0, kl1);
                mma_bf16(sacc[n1][0], sacc[n1][1], sacc[n1][2], sacc[n1][3],
                         qfh[ks][0], qfh[ks][1], qfh[ks][2], qfh[ks][3], kl2, kl3);
                mma_bf16(sacc[n0][0], sacc[n0][1], sacc[n0][2], sacc[n0][3],
                         qfl[ks][0], qfl[ks][1], qfl[ks][2], qfl[ks][3], kh0, kh1);
                mma_bf16(sacc[n1][0], sacc[n1][1], sacc[n1][2], sacc[n1][3],
                         qfl[ks][0], qfl[ks][1], qfl[ks][2], qfl[ks][3], kh2, kh3);
            }
        }

        uint32_t pph[16][2], ppl[16][2];
#pragma unroll
        for (int nt = 0; nt < 16; nt++) {
            int jj0 = nt * 8 + jj_b, jj1 = jj0 + 1;
            float p0 = __expf(sacc[nt][0] * 0.125f);
            float p1 = __expf(sacc[nt][1] * 0.125f);
            float p2 = __expf(sacc[nt][2] * 0.125f);
            float p3 = __expf(sacc[nt][3] * 0.125f);
            if (ch == 0) {
                if (jj0 < i_lo) p0 = 0.f;
                if (jj1 < i_lo) p1 = 0.f;
                if (jj0 < i_hi) p2 = 0.f;
                if (jj1 < i_hi) p3 = 0.f;
            } else if (ch == 2) {
                if (jj0 > i_lo) p0 = 0.f;
                if (jj1 > i_lo) p1 = 0.f;
                if (jj0 > i_hi) p2 = 0.f;
                if (jj1 > i_hi) p3 = 0.f;
            }
            ls0 += p0 + p1;
            ls1 += p2 + p3;
            uint16_t h0, l0, h1, l1;
            bf16_split(p0, h0, l0); bf16_split(p1, h1, l1);
            pph[nt][0] = pack2(h0, h1);
            ppl[nt][0] = pack2(l0, l1);
            bf16_split(p2, h0, l0); bf16_split(p3, h1, l1);
            pph[nt][1] = pack2(h0, h1);
            ppl[nt][1] = pack2(l0, l1);
        }

#pragma unroll
        for (int ks = 0; ks < 8; ks++) {
            uint32_t a0 = pph[2 * ks][0], a1 = pph[2 * ks][1];
            uint32_t a2 = pph[2 * ks + 1][0], a3 = pph[2 * ks + 1][1];
            uint32_t c0 = ppl[2 * ks][0], c1 = ppl[2 * ks][1];
            uint32_t c2 = ppl[2 * ks + 1][0], c3 = ppl[2 * ks + 1][1];
#pragma unroll
            for (int ng = 0; ng < 4; ng++) {
                uint32_t vh0, vh1, vh2, vh3, vl0, vl1, vl2, vl3;
                uint32_t ad = sb + OFF_VH + (ks * 16 + v_kr) * AT_STR + (ng * 16 + v_nc) * 2;
                ldm_x4_t(vh0, vh1, vh2, vh3, ad);
                ldm_x4_t(vl0, vl1, vl2, vl3, ad + (OFF_VL - OFF_VH));
                int d0 = ng * 2, d1 = ng * 2 + 1;
                mma_bf16(o[d0][0], o[d0][1], o[d0][2], o[d0][3], a0, a1, a2, a3, vh0, vh1);
                mma_bf16(o[d1][0], o[d1][1], o[d1][2], o[d1][3], a0, a1, a2, a3, vh2, vh3);
                mma_bf16(o[d0][0], o[d0][1], o[d0][2], o[d0][3], a0, a1, a2, a3, vl0, vl1);
                mma_bf16(o[d1][0], o[d1][1], o[d1][2], o[d1][3], a0, a1, a2, a3, vl2, vl3);
                mma_bf16(o[d0][0], o[d0][1], o[d0][2], o[d0][3], c0, c1, c2, c3, vh0, vh1);
                mma_bf16(o[d1][0], o[d1][1], o[d1][2], o[d1][3], c0, c1, c2, c3, vh2, vh3);
            }
        }
    }

    ls0 += __shfl_xor_sync(0xffffffffu, ls0, 1);
    ls0 += __shfl_xor_sync(0xffffffffu, ls0, 2);
    ls1 += __shfl_xor_sync(0xffffffffu, ls1, 1);
    ls1 += __shfl_xor_sync(0xffffffffu, ls1, 2);
    float inv0 = 1.f / ls0, inv1 = 1.f / ls1;

    const int qg0 = qt * QT + i_lo;
#pragma unroll
    for (int dt = 0; dt < 8; dt++) {
        int d = h * HDq + dt * 8 + jj_b;
        size_t base0 = (size_t)(b * Lq + qg0) * Dq + d;
        size_t base1 = base0 + (size_t)8 * Dq;
        uint16_t h0, l0, h1, l1;
        bf16_split(o[dt][0] * inv0, h0, l0);
        bf16_split(o[dt][1] * inv0, h1, l1);
        *(uint32_t*)(ohi + base0) = pack2(h0, h1);
        *(uint32_t*)(olo + base0) = pack2(l0, l1);
        bf16_split(o[dt][2] * inv1, h0, l0);
        bf16_split(o[dt][3] * inv1, h1, l1);
        *(uint32_t*)(ohi + base1) = pack2(h0, h1);
        *(uint32_t*)(olo + base1) = pack2(l0, l1);
    }
}

// ---------------------------------------------------------------------------
extern "C" void kernel_launch(void* const* d_in, const int* in_sizes, int n_in,
                              void* d_out, int out_size)
{
    const float* x     = (const float*)d_in[0];
    const float* w_qkv = (const float*)d_in[1];
    const float* b_qkv = (const float*)d_in[2];
    const float* w_out = (const float*)d_in[3];
    const float* b_out = (const float*)d_in[4];
    float* out = (float*)d_out;

    __nv_bfloat16 *qkvh, *qkvl, *xhi, *xlo, *whi, *wlo, *ohi, *olo, *ahi, *alo;
    cudaGetSymbolAddress((void**)&qkvh, g_qkvh);
    cudaGetSymbolAddress((void**)&qkvl, g_qkvl);
    cudaGetSymbolAddress((void**)&xhi, g_x_hi);
    cudaGetSymbolAddress((void**)&xlo, g_x_lo);
    cudaGetSymbolAddress((void**)&whi, g_wqkv_hi);
    cudaGetSymbolAddress((void**)&wlo, g_wqkv_lo);
    cudaGetSymbolAddress((void**)&ohi, g_wout_hi);
    cudaGetSymbolAddress((void**)&olo, g_wout_lo);
    cudaGetSymbolAddress((void**)&ahi, g_attn_hi);
    cudaGetSymbolAddress((void**)&alo, g_attn_lo);

    const int M = Bq * Lq;    // 4096

    cudaFuncSetAttribute(gemm_bf16x3_pre<true>,  cudaFuncAttributeMaxDynamicSharedMemorySize, SMEM_GEMM_BYTES);
    cudaFuncSetAttribute(gemm_bf16x3_pre<false>, cudaFuncAttributeMaxDynamicSharedMemorySize, SMEM_GEMM_BYTES);
    cudaFuncSetAttribute(attn_flash, cudaFuncAttributeMaxDynamicSharedMemorySize, SMEM_ATT);

    // 0) pre-split inputs
    split_bf16<<<(M * Dq) / 1024, 256>>>(x, xhi, xlo, M * Dq);
    split_bf16<<<(Dq * 3 * Dq) / 1024, 256>>>(w_qkv, whi, wlo, Dq * 3 * Dq);
    split_bf16<<<(Dq * Dq) / 1024, 256>>>(w_out, ohi, olo, Dq * Dq);

    // 1) QKV projection -> bf16 hi/lo planes
    {
        dim3 grid(3 * Dq / 128, M / 128);
        gemm_bf16x3_pre<true><<<grid, 512, SMEM_GEMM_BYTES>>>(
            xhi, xlo, whi, wlo, b_qkv, nullptr, qkvh, qkvl, M, 3 * Dq, Dq);
    }

    // 2) Tensor-core windowed attention -> bf16 hi/lo planes
    {
        dim3 grid(Lq / QT, Hq, Bq);
        attn_flash<<<grid, 256, SMEM_ATT>>>(qkvh, qkvl, ahi, alo);
    }

    // 3) Output projection -> fp32 out
    {
        dim3 grid(Dq / 128, M / 128);
        gemm_bf16x3_pre<false><<<grid, 512, SMEM_GEMM_BYTES>>>(
            ahi, alo, ohi, olo, b_out, out, nullptr, nullptr, M, Dq, Dq);
    }
}

// round 11
// speedup vs baseline: 1.0039x; 1.0039x over previous
#include <cuda_runtime.h>
#include <cuda_bf16.h>
#include <cstdint>
#include <math.h>

#define Bq 2
#define Lq 2048
#define Dq 1024
#define Hq 16
#define HDq 64
#define HALFW 128
#define QT 128

// Scratch (no cudaMalloc allowed)
__device__ __nv_bfloat16 g_qkvh[(size_t)Bq * Lq * 3 * Dq];
__device__ __nv_bfloat16 g_qkvl[(size_t)Bq * Lq * 3 * Dq];
__device__ __nv_bfloat16 g_x_hi[(size_t)Bq * Lq * Dq];
__device__ __nv_bfloat16 g_x_lo[(size_t)Bq * Lq * Dq];
__device__ __nv_bfloat16 g_wqkv_hi[(size_t)Dq * 3 * Dq];
__device__ __nv_bfloat16 g_wqkv_lo[(size_t)Dq * 3 * Dq];
__device__ __nv_bfloat16 g_wout_hi[(size_t)Dq * Dq];
__device__ __nv_bfloat16 g_wout_lo[(size_t)Dq * Dq];
__device__ __nv_bfloat16 g_attn_hi[(size_t)Bq * Lq * Dq];
__device__ __nv_bfloat16 g_attn_lo[(size_t)Bq * Lq * Dq];

// ===========================================================================
// helpers
// ===========================================================================
__device__ __forceinline__ void bf16_split(float x, uint16_t& hi, uint16_t& lo) {
    __nv_bfloat16 h = __float2bfloat16(x);
    float hf = __bfloat162float(h);
    __nv_bfloat16 l = __float2bfloat16(x - hf);
    hi = __nv_bfloat16_raw(h).x;
    lo = __nv_bfloat16_raw(l).x;
}

__device__ __forceinline__ uint32_t pack2(uint16_t a, uint16_t b) {
    return (uint32_t)a | ((uint32_t)b << 16);
}

__device__ __forceinline__ uint32_t smem_u32(const void* p) {
    uint32_t a;
    asm("{ .reg .u64 t; cvta.to.shared.u64 t, %1; cvt.u32.u64 %0, t; }" : "=r"(a) : "l"(p));
    return a;
}

__device__ __forceinline__ void ldm_x4(uint32_t& r0, uint32_t& r1, uint32_t& r2, uint32_t& r3,
                                       uint32_t addr) {
    asm volatile("ldmatrix.sync.aligned.m8n8.x4.shared.b16 {%0,%1,%2,%3}, [%4];"
                 : "=r"(r0), "=r"(r1), "=r"(r2), "=r"(r3) : "r"(addr));
}
__device__ __forceinline__ void ldm_x4_t(uint32_t& r0, uint32_t& r1, uint32_t& r2, uint32_t& r3,
                                         uint32_t addr) {
    asm volatile("ldmatrix.sync.aligned.m8n8.x4.trans.shared.b16 {%0,%1,%2,%3}, [%4];"
                 : "=r"(r0), "=r"(r1), "=r"(r2), "=r"(r3) : "r"(addr));
}

__device__ __forceinline__ void mma_bf16(float& d0, float& d1, float& d2, float& d3,
                                         uint32_t a0, uint32_t a1, uint32_t a2, uint32_t a3,
                                         uint32_t b0, uint32_t b1) {
    asm volatile(
        "mma.sync.aligned.m16n8k16.row.col.f32.bf16.bf16.f32 "
        "{%0,%1,%2,%3}, {%4,%5,%6,%7}, {%8,%9}, {%0,%1,%2,%3};"
        : "+f"(d0), "+f"(d1), "+f"(d2), "+f"(d3)
        : "r"(a0), "r"(a1), "r"(a2), "r"(a3), "r"(b0), "r"(b1));
}

__device__ __forceinline__ void cp16(uint32_t s, const void* g) {
    asm volatile("cp.async.cg.shared.global [%0], [%1], 16;" :: "r"(s), "l"(g) : "memory");
}
#define CP_COMMIT() asm volatile("cp.async.commit_group;" ::: "memory")
#define CP_WAIT1()  asm volatile("cp.async.wait_group 1;" ::: "memory")

// ===========================================================================
// split kernel: fp32 -> bf16 hi + lo
// ===========================================================================
__global__ void __launch_bounds__(256)
split_bf16(const float* __restrict__ in, __nv_bfloat16* __restrict__ hi,
           __nv_bfloat16* __restrict__ lo, int n)
{
    int i = (blockIdx.x * 256 + threadIdx.x) * 4;
    if (i >= n) return;
    float4 v = *(const float4*)(in + i);
    uint16_t h0, l0, h1, l1, h2, l2, h3, l3;
    bf16_split(v.x, h0, l0);
    bf16_split(v.y, h1, l1);
    bf16_split(v.z, h2, l2);
    bf16_split(v.w, h3, l3);
    *(uint2*)(hi + i) = make_uint2(pack2(h0, h1), pack2(h2, h3));
    *(uint2*)(lo + i) = make_uint2(pack2(l0, l1), pack2(l2, l3));
}

// ===========================================================================
// bf16x3 GEMM, CTA tile 128x256, 8 warps of 64x64 (2x4), cp.async pipeline.
// 3 passes: Ahi·Bhi + Ahi·Blo + Alo·Bhi.  K-chunk 32, double buffered.
// ===========================================================================
#define A_STRIDE 40          // bf16 elems per A row (80 B)
#define B_STRIDE 264         // bf16 elems per B row (528 B)
#define A_PLANE  (128 * A_STRIDE * 2)     // 10240 B
#define B_PLANE  (32 * B_STRIDE * 2)      // 16896 B
#define OFF_AHI  0
#define OFF_ALO  (A_PLANE)
#define OFF_BHI  (2 * A_PLANE)
#define OFF_BLO  (2 * A_PLANE + B_PLANE)
#define BUF_BYTES (2 * A_PLANE + 2 * B_PLANE)   // 54272
#define SMEM_GEMM_BYTES (2 * BUF_BYTES)          // 108544

template<bool SPLIT_OUT>
__global__ void __launch_bounds__(256, 1)
gemm_bf16x3_pre(const __nv_bfloat16* __restrict__ Ahi, const __nv_bfloat16* __restrict__ Alo,
                const __nv_bfloat16* __restrict__ Bhi, const __nv_bfloat16* __restrict__ Blo,
                const float* __restrict__ bias, float* __restrict__ C,
                __nv_bfloat16* __restrict__ Chi, __nv_bfloat16* __restrict__ Clo,
                int M, int N, int K)
{
    extern __shared__ char smem[];
    const uint32_t sbase = smem_u32(smem);
    const int t    = threadIdx.x;
    const int lane = t & 31;
    const int wid  = t >> 5;
    const int warp_m = wid >> 2;      // 0..1 (x64 rows)
    const int warp_n = wid & 3;       // 0..3 (x64 cols)

    const int n0 = blockIdx.x * 256;
    const int m0 = blockIdx.y * 128;

    float acc[4][8][4];               // [mt][nt][frag] = 128 regs
#pragma unroll
    for (int i = 0; i < 4; i++)
#pragma unroll
        for (int j = 0; j < 8; j++)
#pragma unroll
            for (int r = 0; r < 4; r++) acc[i][j][r] = 0.f;

    // cp.async loader mappings
    const int la_r = t >> 2, la_g = t & 3;        // A: 2 passes of (row, 8-col group)
    const int lb_k = t >> 3, lb_g = t & 7;        // B: 4 passes of (k-row, 8-col group)

    // issue one chunk's cp.asyncs
    auto issue_chunk = [&](int c) {
        const int k0 = c * 32;
        const uint32_t buf = sbase + (c & 1) * BUF_BYTES;
#pragma unroll
        for (int p = 0; p < 2; p++) {
            int row = la_r + p * 64;
            uint32_t sa = buf + OFF_AHI + row * (A_STRIDE * 2) + la_g * 16;
            cp16(sa, Ahi + (size_t)(m0 + row) * K + k0 + la_g * 8);
            cp16(sa + (OFF_ALO - OFF_AHI), Alo + (size_t)(m0 + row) * K + k0 + la_g * 8);
        }
#pragma unroll
        for (int p = 0; p < 4; p++) {
            int ng = lb_g + p * 8;
            uint32_t sb = buf + OFF_BHI + lb_k * (B_STRIDE * 2) + ng * 16;
            cp16(sb, Bhi + (size_t)(k0 + lb_k) * N + n0 + ng * 8);
            cp16(sb + (OFF_BLO - OFF_BHI), Blo + (size_t)(k0 + lb_k) * N + n0 + ng * 8);
        }
    };

    const int NCH = K / 32;
    issue_chunk(0);
    CP_COMMIT();

    for (int c = 0; c < NCH; c++) {
        __syncthreads();                 // all warps done reading buf[(c-1)&1]
        if (c + 1 < NCH) issue_chunk(c + 1);
        CP_COMMIT();
        CP_WAIT1();                      // group c complete
        __syncthreads();                 // publish to all warps

        const uint32_t buf = sbase + (c & 1) * BUF_BYTES;
#pragma unroll
        for (int kk = 0; kk < 2; kk++) {
            const int a_row = (lane & 15);
            const int a_cb  = (lane >> 4);
            const int b_kr  = kk * 16 + (lane & 15);
            const int b_nc  = (lane & 16) ? 8 : 0;

            uint32_t af[4][4], bh[4][4], bl[4];
            // A-hi frags (4 x 16 rows)
#pragma unroll
            for (int mt = 0; mt < 4; mt++) {
                int row = warp_m * 64 + mt * 16 + a_row;
                uint32_t ad = buf + OFF_AHI + (row * A_STRIDE + kk * 16 + a_cb * 8) * 2;
                ldm_x4(af[mt][0], af[mt][1], af[mt][2], af[mt][3], ad);
            }
            // B-hi frags (4 x 16 cols), resident for passes 1 and 3
#pragma unroll
            for (int nb = 0; nb < 4; nb++) {
                int ncol = warp_n * 64 + nb * 16 + b_nc;
                uint32_t bd = buf + OFF_BHI + (b_kr * B_STRIDE + ncol) * 2;
                ldm_x4_t(bh[nb][0], bh[nb][1], bh[nb][2], bh[nb][3], bd);
            }
            // pass 1: Ahi * Bhi
#pragma unroll
            for (int mt = 0; mt < 4; mt++)
#pragma unroll
                for (int nt = 0; nt < 8; nt++) {
                    int nb = nt >> 1, half = nt & 1;
                    mma_bf16(acc[mt][nt][0], acc[mt][nt][1], acc[mt][nt][2], acc[mt][nt][3],
                             af[mt][0], af[mt][1], af[mt][2], af[mt][3],
                             bh[nb][half * 2], bh[nb][half * 2 + 1]);
                }
            // pass 2: Ahi * Blo (B-lo streamed per nb)
#pragma unroll
            for (int nb = 0; nb < 4; nb++) {
                int ncol = warp_n * 64 + nb * 16 + b_nc;
                uint32_t bd = buf + OFF_BLO + (b_kr * B_STRIDE + ncol) * 2;
                ldm_x4_t(bl[0], bl[1], bl[2], bl[3], bd);
#pragma unroll
                for (int mt = 0; mt < 4; mt++)
#pragma unroll
                    for (int half = 0; half < 2; half++) {
                        int nt = nb * 2 + half;
                        mma_bf16(acc[mt][nt][0], acc[mt][nt][1], acc[mt][nt][2], acc[mt][nt][3],
                                 af[mt][0], af[mt][1], af[mt][2], af[mt][3],
                                 bl[half * 2], bl[half * 2 + 1]);
                    }
            }
            // pass 3: Alo * Bhi (A-lo reloaded into af regs)
#pragma unroll
            for (int mt = 0; mt < 4; mt++) {
                int row = warp_m * 64 + mt * 16 + a_row;
                uint32_t ad = buf + OFF_ALO + (row * A_STRIDE + kk * 16 + a_cb * 8) * 2;
                ldm_x4(af[mt][0], af[mt][1], af[mt][2], af[mt][3], ad);
            }
#pragma unroll
            for (int mt = 0; mt < 4; mt++)
#pragma unroll
                for (int nt = 0; nt < 8; nt++) {
                    int nb = nt >> 1, half = nt & 1;
                    mma_bf16(acc[mt][nt][0], acc[mt][nt][1], acc[mt][nt][2], acc[mt][nt][3],
                             af[mt][0], af[mt][1], af[mt][2], af[mt][3],
                             bh[nb][half * 2], bh[nb][half * 2 + 1]);
                }
        }
    }

    // ---- epilogue ----
    const int r_base = m0 + warp_m * 64 + (lane >> 2);
    const int c_base = n0 + warp_n * 64 + 2 * (lane & 3);
#pragma unroll
    for (int mt = 0; mt < 4; mt++) {
#pragma unroll
        for (int nt = 0; nt < 8; nt++) {
            int col = c_base + nt * 8;
            float b0 = bias[col], b1 = bias[col + 1];
            int r0 = r_base + mt * 16;
            float v00 = acc[mt][nt][0] + b0, v01 = acc[mt][nt][1] + b1;
            float v10 = acc[mt][nt][2] + b0, v11 = acc[mt][nt][3] + b1;
            if (SPLIT_OUT) {
                uint16_t h0, l0, h1, l1;
                bf16_split(v00, h0, l0); bf16_split(v01, h1, l1);
                *(uint32_t*)(Chi + (size_t)r0 * N + col) = pack2(h0, h1);
                *(uint32_t*)(Clo + (size_t)r0 * N + col) = pack2(l0, l1);
                bf16_split(v10, h0, l0); bf16_split(v11, h1, l1);
                *(uint32_t*)(Chi + (size_t)(r0 + 8) * N + col) = pack2(h0, h1);
                *(uint32_t*)(Clo + (size_t)(r0 + 8) * N + col) = pack2(l0, l1);
            } else {
                *(float2*)(C + (size_t)r0 * N + col)       = make_float2(v00, v01);
                *(float2*)(C + (size_t)(r0 + 8) * N + col) = make_float2(v10, v11);
            }
        }
    }
}

// ===========================================================================
// Tensor-core windowed flash attention (unchanged from round 9 — passing)
// ===========================================================================
#define AT_STR 144
#define OFF_KH 0
#define OFF_KL 18432
#define OFF_VH 36864
#define OFF_VL 55296
#define SMEM_ATT 73728

__global__ void __launch_bounds__(256, 1)
attn_flash(const __nv_bfloat16* __restrict__ qh_g, const __nv_bfloat16* __restrict__ ql_g,
           __nv_bfloat16* __restrict__ ohi, __nv_bfloat16* __restrict__ olo)
{
    extern __shared__ char smem[];
    const uint32_t sb = smem_u32(smem);
    const int qt = blockIdx.x, h = blockIdx.y, b = blockIdx.z;
    const int t = threadIdx.x, lane = t & 31, wid = t >> 5;

#pragma unroll
    for (int p = 0; p < 8; p++) {
        int idx = t + p * 256;
        int pl = idx >> 10, rem = idx & 1023, row = rem >> 3, g = rem & 7;
        const __nv_bfloat16* src = (pl ? ql_g : qh_g)
            + ((size_t)(b * Lq + qt * QT + row) * 3 + 0) * Dq + h * HDq + g * 8;
        uint4 v = *(const uint4*)src;
        uint32_t dst = sb + (pl ? OFF_KL : OFF_KH) + row * AT_STR + g * 16;
        asm volatile("st.shared.v4.b32 [%0], {%1,%2,%3,%4};" ::
                     "r"(dst), "r"(v.x), "r"(v.y), "r"(v.z), "r"(v.w) : "memory");
    }
    __syncthreads();

    uint32_t qfh[4][4], qfl[4][4];
    {
        int a_row = lane & 15, a_cb = lane >> 4;
        int qrow = wid * 16 + a_row;
#pragma unroll
        for (int ks = 0; ks < 4; ks++) {
            uint32_t ad = sb + OFF_KH + qrow * AT_STR + (ks * 16 + a_cb * 8) * 2;
            ldm_x4(qfh[ks][0], qfh[ks][1], qfh[ks][2], qfh[ks][3], ad);
            ldm_x4(qfl[ks][0], qfl[ks][1], qfl[ks][2], qfl[ks][3], ad + (OFF_KL - OFF_KH));
        }
    }

    float o[8][4];
#pragma unroll
    for (int i = 0; i < 8; i++)
#pragma unroll
        for (int r = 0; r < 4; r++) o[i][r] = 0.f;
    float ls0 = 0.f, ls1 = 0.f;

    const int i_lo = wid * 16 + (lane >> 2);
    const int i_hi = i_lo + 8;
    const int jj_b = (lane & 3) * 2;

    const int bn_row = (lane & 7) + ((lane & 16) >> 1);
    const int bk_off = (lane & 8);
    const int v_kr = (lane & 15);
    const int v_nc = (lane & 16) ? 8 : 0;

    for (int ch = 0; ch < 3; ch++) {
        if (ch == 0 && qt == 0) continue;
        if (ch == 2 && qt == (Lq / QT) - 1) continue;
        const int jbase = qt * QT + (ch - 1) * 128;

        __syncthreads();
#pragma unroll
        for (int p = 0; p < 16; p++) {
            int idx = t + p * 256;
            int plane = idx >> 10, rem = idx & 1023, row = rem >> 3, g = rem & 7;
            int which = (plane < 2) ? 1 : 2;
            const __nv_bfloat16* src = ((plane & 1) ? ql_g : qh_g)
                + ((size_t)(b * Lq + jbase + row) * 3 + which) * Dq + h * HDq + g * 8;
            uint4 v = *(const uint4*)src;
            uint32_t off = (plane == 0) ? OFF_KH : (plane == 1) ? OFF_KL
                         : (plane == 2) ? OFF_VH : OFF_VL;
            uint32_t dst = sb + off + row * AT_STR + g * 16;
            asm volatile("st.shared.v4.b32 [%0], {%1,%2,%3,%4};" ::
                         "r"(dst), "r"(v.x), "r"(v.y), "r"(v.z), "r"(v.w) : "memory");
        }
        __syncthreads();

        float sacc[16][4];
#pragma unroll
        for (int i = 0; i < 16; i++)
#pragma unroll
            for (int r = 0; r < 4; r++) sacc[i][r] = 0.f;

#pragma unroll
        for (int ks = 0; ks < 4; ks++) {
#pragma unroll
            for (int ng = 0; ng < 8; ng++) {
                uint32_t kh0, kh1, kh2, kh3, kl0, kl1, kl2, kl3;
                uint32_t ad = sb + OFF_KH + (ng * 16 + bn_row) * AT_STR + (ks * 16 + bk_off) * 2;
                ldm_x4(kh0, kh1, kh2, kh3, ad);
                ldm_x4(kl0, kl1, kl2, kl3, ad + (OFF_KL - OFF_KH));
                int n0 = ng * 2, n1 = ng * 2 + 1;
                mma_bf16(sacc[n0][0], sacc[n0][1], sacc[n0][2], sacc[n0][3],
                         qfh[ks][0], qfh[ks][1], qfh[ks][2], qfh[ks][3], kh0, kh1);
                mma_bf16(sacc[n1][0], sacc[n1][1], sacc[n1][2], sacc[n1][3],
                         qfh[ks][0], qfh[ks][1], qfh[ks][2], qfh[ks][3], kh2, kh3);
                mma_bf16(sacc[n0][0], sacc[n0][1], sacc[n0][2], sacc[n0][3],
                         qfh[ks][0], qfh[ks][1], qfh[ks][2], qfh[ks][3], kl0, kl1);
                mma_bf16(sacc[n1][0], sacc[n1][1], sacc[n1][2], sacc[n1][3],
                         qfh[ks][0], qfh[ks][1], qfh[ks][2], qfh[ks][3], kl2, kl3);
                mma_bf16(sacc[n0][0], sacc[n0][1], sacc[n0][2], sacc[n0][3],
                         qfl[ks][0], qfl[ks][1], qfl[ks][2], qfl[ks][3], kh0, kh1);
                mma_bf16(sacc[n1][0], sacc[n1][1], sacc[n1][2], sacc[n1][3],
                         qfl[ks][0], qfl[ks][1], qfl[ks][2], qfl[ks][3], kh2, kh3);
            }
        }

        uint32_t pph[16][2], ppl[16][2];
#pragma unroll
        for (int nt = 0; nt < 16; nt++) {
            int jj0 = nt * 8 + jj_b, jj1 = jj0 + 1;
            float p0 = __expf(sacc[nt][0] * 0.125f);
            float p1 = __expf(sacc[nt][1] * 0.125f);
            float p2 = __expf(sacc[nt][2] * 0.125f);
            float p3 = __expf(sacc[nt][3] * 0.125f);
            if (ch == 0) {
                if (jj0 < i_lo) p0 = 0.f;
                if (jj1 < i_lo) p1 = 0.f;
                if (jj0 < i_hi) p2 = 0.f;
                if (jj1 < i_hi) p3 = 0.f;
            } else if (ch == 2) {
                if (jj0 > i_lo) p0 = 0.f;
                if (jj1 > i_lo) p1 = 0.f;
                if (jj0 > i_hi) p2 = 0.f;
                if (jj1 > i_hi) p3 = 0.f;
            }
            ls0 += p0 + p1;
            ls1 += p2 + p3;
            uint16_t h0, l0, h1, l1;
            bf16_split(p0, h0, l0); bf16_split(p1, h1, l1);
            pph[nt][0] = pack2(h0, h1);
            ppl[nt][0] = pack2(l0, l1);
            bf16_split(p2, h0, l0); bf16_split(p3, h1, l1);
            pph[nt][1] = pack2(h0, h1);
            ppl[nt][1] = pack2(l0, l1);
        }

#pragma unroll
        for (int ks = 0; ks < 8; ks++) {
            uint32_t a0 = pph[2 * ks][0], a1 = pph[2 * ks][1];
            uint32_t a2 = pph[2 * ks + 1][0], a3 = pph[2 * ks + 1][1];
            uint32_t c0 = ppl[2 * ks][0], c1 = ppl[2 * ks][1];
            uint32_t c2 = ppl[2 * ks + 1][0], c3 = ppl[2 * ks + 1][1];
#pragma unroll
            for (int ng = 0; ng < 4; ng++) {
                uint32_t vh0, vh1, vh2, vh3, vl0, vl1, vl2, vl3;
                uint32_t ad = sb + OFF_VH + (ks * 16 + v_kr) * AT_STR + (ng * 16 + v_nc) * 2;
                ldm_x4_t(vh0, vh1, vh2, vh3, ad);
                ldm_x4_t(vl0, vl1, vl2, vl3, ad + (OFF_VL - OFF_VH));
                int d0 = ng * 2, d1 = ng * 2 + 1;
                mma_bf16(o[d0][0], o[d0][1], o[d0][2], o[d0][3], a0, a1, a2, a3, vh0, vh1);
                mma_bf16(o[d1][0], o[d1][1], o[d1][2], o[d1][3], a0, a1, a2, a3, vh2, vh3);
                mma_bf16(o[d0][0], o[d0][1], o[d0][2], o[d0][3], a0, a1, a2, a3, vl0, vl1);
                mma_bf16(o[d1][0], o[d1][1], o[d1][2], o[d1][3], a0, a1, a2, a3, vl2, vl3);
                mma_bf16(o[d0][0], o[d0][1], o[d0][2], o[d0][3], c0, c1, c2, c3, vh0, vh1);
                mma_bf16(o[d1][0], o[d1][1], o[d1][2], o[d1][3], c0, c1, c2, c3, vh2, vh3);
            }
        }
    }

    ls0 += __shfl_xor_sync(0xffffffffu, ls0, 1);
    ls0 += __shfl_xor_sync(0xffffffffu, ls0, 2);
    ls1 += __shfl_xor_sync(0xffffffffu, ls1, 1);
    ls1 += __shfl_xor_sync(0xffffffffu, ls1, 2);
    float inv0 = 1.f / ls0, inv1 = 1.f / ls1;

    const int qg0 = qt * QT + i_lo;
#pragma unroll
    for (int dt = 0; dt < 8; dt++) {
        int d = h * HDq + dt * 8 + jj_b;
        size_t base0 = (size_t)(b * Lq + qg0) * Dq + d;
        size_t base1 = base0 + (size_t)8 * Dq;
        uint16_t h0, l0, h1, l1;
        bf16_split(o[dt][0] * inv0, h0, l0);
        bf16_split(o[dt][1] * inv0, h1, l1);
        *(uint32_t*)(ohi + base0) = pack2(h0, h1);
        *(uint32_t*)(olo + base0) = pack2(l0, l1);
        bf16_split(o[dt][2] * inv1, h0, l0);
        bf16_split(o[dt][3] * inv1, h1, l1);
        *(uint32_t*)(ohi + base1) = pack2(h0, h1);
        *(uint32_t*)(olo + base1) = pack2(l0, l1);
    }
}

// ---------------------------------------------------------------------------
extern "C" void kernel_launch(void* const* d_in, const int* in_sizes, int n_in,
                              void* d_out, int out_size)
{
    const float* x     = (const float*)d_in[0];
    const float* w_qkv = (const float*)d_in[1];
    const float* b_qkv = (const float*)d_in[2];
    const float* w_out = (const float*)d_in[3];
    const float* b_out = (const float*)d_in[4];
    float* out = (float*)d_out;

    __nv_bfloat16 *qkvh, *qkvl, *xhi, *xlo, *whi, *wlo, *ohi, *olo, *ahi, *alo;
    cudaGetSymbolAddress((void**)&qkvh, g_qkvh);
    cudaGetSymbolAddress((void**)&qkvl, g_qkvl);
    cudaGetSymbolAddress((void**)&xhi, g_x_hi);
    cudaGetSymbolAddress((void**)&xlo, g_x_lo);
    cudaGetSymbolAddress((void**)&whi, g_wqkv_hi);
    cudaGetSymbolAddress((void**)&wlo, g_wqkv_lo);
    cudaGetSymbolAddress((void**)&ohi, g_wout_hi);
    cudaGetSymbolAddress((void**)&olo, g_wout_lo);
    cudaGetSymbolAddress((void**)&ahi, g_attn_hi);
    cudaGetSymbolAddress((void**)&alo, g_attn_lo);

    const int M = Bq * Lq;    // 4096

    cudaFuncSetAttribute(gemm_bf16x3_pre<true>,  cudaFuncAttributeMaxDynamicSharedMemorySize, SMEM_GEMM_BYTES);
    cudaFuncSetAttribute(gemm_bf16x3_pre<false>, cudaFuncAttributeMaxDynamicSharedMemorySize, SMEM_GEMM_BYTES);
    cudaFuncSetAttribute(attn_flash, cudaFuncAttributeMaxDynamicSharedMemorySize, SMEM_ATT);

    // 0) pre-split inputs
    split_bf16<<<(M * Dq) / 1024, 256>>>(x, xhi, xlo, M * Dq);
    split_bf16<<<(Dq * 3 * Dq) / 1024, 256>>>(w_qkv, whi, wlo, Dq * 3 * Dq);
    split_bf16<<<(Dq * Dq) / 1024, 256>>>(w_out, ohi, olo, Dq * Dq);

    // 1) QKV projection -> bf16 hi/lo planes
    {
        dim3 grid(3 * Dq / 256, M / 128);   // 12 x 32
        gemm_bf16x3_pre<true><<<grid, 256, SMEM_GEMM_BYTES>>>(
            xhi, xlo, whi, wlo, b_qkv, nullptr, qkvh, qkvl, M, 3 * Dq, Dq);
    }

    // 2) Tensor-core windowed attention -> bf16 hi/lo planes
    {
        dim3 grid(Lq / QT, Hq, Bq);
        attn_flash<<<grid, 256, SMEM_ATT>>>(qkvh, qkvl, ahi, alo);
    }

    // 3) Output projection -> fp32 out
    {
        dim3 grid(Dq / 256, M / 128);       // 4 x 32
        gemm_bf16x3_pre<false><<<grid, 256, SMEM_GEMM_BYTES>>>(
            ahi, alo, ohi, olo, b_out, out, nullptr, nullptr, M, Dq, Dq);
    }
}

// round 12
// speedup vs baseline: 1.4142x; 1.4087x over previous
#include <cuda_runtime.h>
#include <cuda_fp16.h>
#include <cstdint>
#include <math.h>

#define Bq 2
#define Lq 2048
#define Dq 1024
#define Hq 16
#define HDq 64
#define HALFW 128
#define QT 128

// Scratch (no cudaMalloc allowed)
__device__ __half g_qkvh[(size_t)Bq * Lq * 3 * Dq];   // [B,L,3,D] hi plane
__device__ __half g_qkvl[(size_t)Bq * Lq * 3 * Dq];   // lo plane
__device__ __half g_x_h[(size_t)Bq * Lq * Dq];        // x single fp16
__device__ __half g_wqkv_hi[(size_t)Dq * 3 * Dq];
__device__ __half g_wqkv_lo[(size_t)Dq * 3 * Dq];
__device__ __half g_wout_hi[(size_t)Dq * Dq];
__device__ __half g_wout_lo[(size_t)Dq * Dq];
__device__ __half g_attn_h[(size_t)Bq * Lq * Dq];     // attention out single fp16

// ===========================================================================
// helpers
// ===========================================================================
__device__ __forceinline__ void fp16_split(float x, uint16_t& hi, uint16_t& lo) {
    __half h = __float2half_rn(x);
    float hf = __half2float(h);
    __half l = __float2half_rn(x - hf);
    hi = __half_raw(h).x;
    lo = __half_raw(l).x;
}

__device__ __forceinline__ uint16_t f16_of(float x) {
    return __half_raw(__float2half_rn(x)).x;
}

__device__ __forceinline__ uint32_t pack2(uint16_t a, uint16_t b) {
    return (uint32_t)a | ((uint32_t)b << 16);
}

// pack (flo -> low half, fhi -> high half)
__device__ __forceinline__ uint32_t f16x2_of(float flo, float fhi) {
    uint32_t r;
    asm("cvt.rn.f16x2.f32 %0, %1, %2;" : "=r"(r) : "f"(fhi), "f"(flo));
    return r;
}

__device__ __forceinline__ uint32_t smem_u32(const void* p) {
    uint32_t a;
    asm("{ .reg .u64 t; cvta.to.shared.u64 t, %1; cvt.u32.u64 %0, t; }" : "=r"(a) : "l"(p));
    return a;
}

__device__ __forceinline__ void ldm_x4(uint32_t& r0, uint32_t& r1, uint32_t& r2, uint32_t& r3,
                                       uint32_t addr) {
    asm volatile("ldmatrix.sync.aligned.m8n8.x4.shared.b16 {%0,%1,%2,%3}, [%4];"
                 : "=r"(r0), "=r"(r1), "=r"(r2), "=r"(r3) : "r"(addr));
}
__device__ __forceinline__ void ldm_x4_t(uint32_t& r0, uint32_t& r1, uint32_t& r2, uint32_t& r3,
                                         uint32_t addr) {
    asm volatile("ldmatrix.sync.aligned.m8n8.x4.trans.shared.b16 {%0,%1,%2,%3}, [%4];"
                 : "=r"(r0), "=r"(r1), "=r"(r2), "=r"(r3) : "r"(addr));
}

__device__ __forceinline__ void mma_f16(float& d0, float& d1, float& d2, float& d3,
                                        uint32_t a0, uint32_t a1, uint32_t a2, uint32_t a3,
                                        uint32_t b0, uint32_t b1) {
    asm volatile(
        "mma.sync.aligned.m16n8k16.row.col.f32.f16.f16.f32 "
        "{%0,%1,%2,%3}, {%4,%5,%6,%7}, {%8,%9}, {%0,%1,%2,%3};"
        : "+f"(d0), "+f"(d1), "+f"(d2), "+f"(d3)
        : "r"(a0), "r"(a1), "r"(a2), "r"(a3), "r"(b0), "r"(b1));
}

// ===========================================================================
// conversion kernels
// ===========================================================================
__global__ void __launch_bounds__(256)
split_fp16(const float* __restrict__ in, __half* __restrict__ hi,
           __half* __restrict__ lo, int n)
{
    int i = (blockIdx.x * 256 + threadIdx.x) * 4;
    if (i >= n) return;
    float4 v = *(const float4*)(in + i);
    uint16_t h0, l0, h1, l1, h2, l2, h3, l3;
    fp16_split(v.x, h0, l0);
    fp16_split(v.y, h1, l1);
    fp16_split(v.z, h2, l2);
    fp16_split(v.w, h3, l3);
    *(uint2*)(hi + i) = make_uint2(pack2(h0, h1), pack2(h2, h3));
    *(uint2*)(lo + i) = make_uint2(pack2(l0, l1), pack2(l2, l3));
}

__global__ void __launch_bounds__(256)
conv_fp16(const float* __restrict__ in, __half* __restrict__ out, int n)
{
    int i = (blockIdx.x * 256 + threadIdx.x) * 4;
    if (i >= n) return;
    float4 v = *(const float4*)(in + i);
    *(uint2*)(out + i) = make_uint2(pack2(f16_of(v.x), f16_of(v.y)),
                                    pack2(f16_of(v.z), f16_of(v.w)));
}

// ===========================================================================
// fp16 GEMM, A single plane, B pre-split hi/lo (2 passes).
// CTA 128x128, warp 64x32 (2x4 warps), K-chunk 32, double buffered,
// register prefetch (structure = round-9 passing kernel).
// ===========================================================================
#define A_STRIDE 40          // fp16 elems per A row (80 B)
#define B_STRIDE 136         // fp16 elems per B row (272 B)
#define A_PLANE  (128 * A_STRIDE * 2)     // 10240 B
#define B_PLANE  (32 * B_STRIDE * 2)      // 8704 B
#define OFF_A    0
#define OFF_BHI  (A_PLANE)
#define OFF_BLO  (A_PLANE + B_PLANE)
#define BUF_BYTES (A_PLANE + 2 * B_PLANE)   // 27648
#define SMEM_GEMM_BYTES (2 * BUF_BYTES)      // 55296

template<bool SPLIT_OUT>
__global__ void __launch_bounds__(256, 1)
gemm_f16x2(const __half* __restrict__ Ah,
           const __half* __restrict__ Bhi, const __half* __restrict__ Blo,
           const float* __restrict__ bias, float* __restrict__ C,
           __half* __restrict__ Chi, __half* __restrict__ Clo,
           int M, int N, int K)
{
    extern __shared__ char smem[];
    const uint32_t sbase = smem_u32(smem);
    const int t    = threadIdx.x;
    const int lane = t & 31;
    const int wid  = t >> 5;
    const int warp_m = wid >> 2;
    const int warp_n = wid & 3;

    const int n0 = blockIdx.x * 128;
    const int m0 = blockIdx.y * 128;

    float acc[4][4][4];
#pragma unroll
    for (int i = 0; i < 4; i++)
#pragma unroll
        for (int j = 0; j < 4; j++)
#pragma unroll
            for (int r = 0; r < 4; r++) acc[i][j][r] = 0.f;

    const int a_m0 = t >> 2, a_g = t & 3;
    const int b_k0 = t >> 4, b_ng = t & 15;

    uint4 pa[2], pbh[2], pbl[2];

#pragma unroll
    for (int p = 0; p < 2; p++) {
        int m = a_m0 + p * 64;
        pa[p] = *(const uint4*)(Ah + (size_t)(m0 + m) * K + a_g * 8);
        int k = b_k0 + p * 16;
        pbh[p] = *(const uint4*)(Bhi + (size_t)k * N + n0 + b_ng * 8);
        pbl[p] = *(const uint4*)(Blo + (size_t)k * N + n0 + b_ng * 8);
    }

    const int NCH = K / 32;
    for (int c = 0; c < NCH; c++) {
        const uint32_t buf = sbase + (c & 1) * BUF_BYTES;

#pragma unroll
        for (int p = 0; p < 2; p++) {
            int m = a_m0 + p * 64;
            uint32_t aaddr = buf + OFF_A + m * (A_STRIDE * 2) + a_g * 16;
            asm volatile("st.shared.v4.b32 [%0], {%1,%2,%3,%4};" ::
                "r"(aaddr), "r"(pa[p].x), "r"(pa[p].y), "r"(pa[p].z), "r"(pa[p].w) : "memory");
            int k = b_k0 + p * 16;
            uint32_t baddr = buf + OFF_BHI + k * (B_STRIDE * 2) + b_ng * 16;
            asm volatile("st.shared.v4.b32 [%0], {%1,%2,%3,%4};" ::
                "r"(baddr), "r"(pbh[p].x), "r"(pbh[p].y), "r"(pbh[p].z), "r"(pbh[p].w) : "memory");
            asm volatile("st.shared.v4.b32 [%0], {%1,%2,%3,%4};" ::
                "r"(baddr + (OFF_BLO - OFF_BHI)),
                "r"(pbl[p].x), "r"(pbl[p].y), "r"(pbl[p].z), "r"(pbl[p].w) : "memory");
        }
        __syncthreads();

        if (c + 1 < NCH) {
            int k0n = (c + 1) * 32;
#pragma unroll
            for (int p = 0; p < 2; p++) {
                int m = a_m0 + p * 64;
                pa[p] = *(const uint4*)(Ah + (size_t)(m0 + m) * K + k0n + a_g * 8);
                int k = b_k0 + p * 16;
                pbh[p] = *(const uint4*)(Bhi + (size_t)(k0n + k) * N + n0 + b_ng * 8);
                pbl[p] = *(const uint4*)(Blo + (size_t)(k0n + k) * N + n0 + b_ng * 8);
            }
        }

#pragma unroll
        for (int kk = 0; kk < 2; kk++) {
            const int a_row = (lane & 15);
            const int a_cb  = (lane >> 4);
            const int b_kr  = kk * 16 + (lane & 15);
            const int b_nc  = (lane & 16) ? 8 : 0;

            uint32_t af[4][4], bh[2][4], bl[2][4];
#pragma unroll
            for (int mt = 0; mt < 4; mt++) {
                int row = warp_m * 64 + mt * 16 + a_row;
                uint32_t ad = buf + OFF_A + (row * A_STRIDE + kk * 16 + a_cb * 8) * 2;
                ldm_x4(af[mt][0], af[mt][1], af[mt][2], af[mt][3], ad);
            }
#pragma unroll
            for (int nb = 0; nb < 2; nb++) {
                int ncol = warp_n * 32 + nb * 16 + b_nc;
                uint32_t bd = buf + OFF_BHI + (b_kr * B_STRIDE + ncol) * 2;
                ldm_x4_t(bh[nb][0], bh[nb][1], bh[nb][2], bh[nb][3], bd);
                ldm_x4_t(bl[nb][0], bl[nb][1], bl[nb][2], bl[nb][3], bd + (OFF_BLO - OFF_BHI));
            }
            // pass 1: A·Bhi ; pass 2: A·Blo
#pragma unroll
            for (int mt = 0; mt < 4; mt++)
#pragma unroll
                for (int nt = 0; nt < 4; nt++) {
                    int nb = nt >> 1, half = nt & 1;
                    mma_f16(acc[mt][nt][0], acc[mt][nt][1], acc[mt][nt][2], acc[mt][nt][3],
                            af[mt][0], af[mt][1], af[mt][2], af[mt][3],
                            bh[nb][half * 2], bh[nb][half * 2 + 1]);
                    mma_f16(acc[mt][nt][0], acc[mt][nt][1], acc[mt][nt][2], acc[mt][nt][3],
                            af[mt][0], af[mt][1], af[mt][2], af[mt][3],
                            bl[nb][half * 2], bl[nb][half * 2 + 1]);
                }
        }
    }

    const int r_base = m0 + warp_m * 64 + (lane >> 2);
    const int c_base = n0 + warp_n * 32 + 2 * (lane & 3);
#pragma unroll
    for (int mt = 0; mt < 4; mt++) {
#pragma unroll
        for (int nt = 0; nt < 4; nt++) {
            int col = c_base + nt * 8;
            float b0 = bias[col], b1 = bias[col + 1];
            int r0 = r_base + mt * 16;
            float v00 = acc[mt][nt][0] + b0, v01 = acc[mt][nt][1] + b1;
            float v10 = acc[mt][nt][2] + b0, v11 = acc[mt][nt][3] + b1;
            if (SPLIT_OUT) {
                uint16_t h0, l0, h1, l1;
                fp16_split(v00, h0, l0); fp16_split(v01, h1, l1);
                *(uint32_t*)(Chi + (size_t)r0 * N + col) = pack2(h0, h1);
                *(uint32_t*)(Clo + (size_t)r0 * N + col) = pack2(l0, l1);
                fp16_split(v10, h0, l0); fp16_split(v11, h1, l1);
                *(uint32_t*)(Chi + (size_t)(r0 + 8) * N + col) = pack2(h0, h1);
                *(uint32_t*)(Clo + (size_t)(r0 + 8) * N + col) = pack2(l0, l1);
            } else {
                *(float2*)(C + (size_t)r0 * N + col)       = make_float2(v00, v01);
                *(float2*)(C + (size_t)(r0 + 8) * N + col) = make_float2(v10, v11);
            }
        }
    }
}

// ===========================================================================
// fp16 tensor-core windowed flash attention.
// Q single fp16; K hi/lo (2-pass S); P single fp16; V hi/lo (2-pass PV).
// Output: single fp16 plane. Masks/layout identical to the passing R9 kernel.
// ===========================================================================
#define AT_STR 144
#define OFF_KH 0
#define OFF_KL 18432
#define OFF_VH 36864
#define OFF_VL 55296
#define SMEM_ATT 73728

__global__ void __launch_bounds__(256, 1)
attn_flash(const __half* __restrict__ qh_g, const __half* __restrict__ ql_g,
           __half* __restrict__ oh_g)
{
    extern __shared__ char smem[];
    const uint32_t sb = smem_u32(smem);
    const int qt = blockIdx.x, h = blockIdx.y, b = blockIdx.z;
    const int t = threadIdx.x, lane = t & 31, wid = t >> 5;

    // ---- stage Q tile (hi plane only) into KH region, grab A-frags ----
#pragma unroll
    for (int p = 0; p < 4; p++) {
        int idx = t + p * 256;
        int row = idx >> 3, g = idx & 7;
        const __half* src = qh_g
            + ((size_t)(b * Lq + qt * QT + row) * 3 + 0) * Dq + h * HDq + g * 8;
        uint4 v = *(const uint4*)src;
        uint32_t dst = sb + OFF_KH + row * AT_STR + g * 16;
        asm volatile("st.shared.v4.b32 [%0], {%1,%2,%3,%4};" ::
                     "r"(dst), "r"(v.x), "r"(v.y), "r"(v.z), "r"(v.w) : "memory");
    }
    __syncthreads();

    uint32_t qf[4][4];
    {
        int a_row = lane & 15, a_cb = lane >> 4;
        int qrow = wid * 16 + a_row;
#pragma unroll
        for (int ks = 0; ks < 4; ks++) {
            uint32_t ad = sb + OFF_KH + qrow * AT_STR + (ks * 16 + a_cb * 8) * 2;
            ldm_x4(qf[ks][0], qf[ks][1], qf[ks][2], qf[ks][3], ad);
        }
    }

    float o[8][4];
#pragma unroll
    for (int i = 0; i < 8; i++)
#pragma unroll
        for (int r = 0; r < 4; r++) o[i][r] = 0.f;
    float ls0 = 0.f, ls1 = 0.f;

    const int i_lo = wid * 16 + (lane >> 2);
    const int i_hi = i_lo + 8;
    const int jj_b = (lane & 3) * 2;

    const int bn_row = (lane & 7) + ((lane & 16) >> 1);
    const int bk_off = (lane & 8);
    const int v_kr = (lane & 15);
    const int v_nc = (lane & 16) ? 8 : 0;

    for (int ch = 0; ch < 3; ch++) {
        if (ch == 0 && qt == 0) continue;
        if (ch == 2 && qt == (Lq / QT) - 1) continue;
        const int jbase = qt * QT + (ch - 1) * 128;

        __syncthreads();
#pragma unroll
        for (int p = 0; p < 16; p++) {
            int idx = t + p * 256;
            int plane = idx >> 10, rem = idx & 1023, row = rem >> 3, g = rem & 7;
            int which = (plane < 2) ? 1 : 2;
            const __half* src = ((plane & 1) ? ql_g : qh_g)
                + ((size_t)(b * Lq + jbase + row) * 3 + which) * Dq + h * HDq + g * 8;
            uint4 v = *(const uint4*)src;
            uint32_t off = (plane == 0) ? OFF_KH : (plane == 1) ? OFF_KL
                         : (plane == 2) ? OFF_VH : OFF_VL;
            uint32_t dst = sb + off + row * AT_STR + g * 16;
            asm volatile("st.shared.v4.b32 [%0], {%1,%2,%3,%4};" ::
                         "r"(dst), "r"(v.x), "r"(v.y), "r"(v.z), "r"(v.w) : "memory");
        }
        __syncthreads();

        // ---- S = Q (Khi + Klo)^T : 2 passes ----
        float sacc[16][4];
#pragma unroll
        for (int i = 0; i < 16; i++)
#pragma unroll
            for (int r = 0; r < 4; r++) sacc[i][r] = 0.f;

#pragma unroll
        for (int ks = 0; ks < 4; ks++) {
#pragma unroll
            for (int ng = 0; ng < 8; ng++) {
                uint32_t kh0, kh1, kh2, kh3, kl0, kl1, kl2, kl3;
                uint32_t ad = sb + OFF_KH + (ng * 16 + bn_row) * AT_STR + (ks * 16 + bk_off) * 2;
                ldm_x4(kh0, kh1, kh2, kh3, ad);
                ldm_x4(kl0, kl1, kl2, kl3, ad + (OFF_KL - OFF_KH));
                int n0 = ng * 2, n1 = ng * 2 + 1;
                mma_f16(sacc[n0][0], sacc[n0][1], sacc[n0][2], sacc[n0][3],
                        qf[ks][0], qf[ks][1], qf[ks][2], qf[ks][3], kh0, kh1);
                mma_f16(sacc[n1][0], sacc[n1][1], sacc[n1][2], sacc[n1][3],
                        qf[ks][0], qf[ks][1], qf[ks][2], qf[ks][3], kh2, kh3);
                mma_f16(sacc[n0][0], sacc[n0][1], sacc[n0][2], sacc[n0][3],
                        qf[ks][0], qf[ks][1], qf[ks][2], qf[ks][3], kl0, kl1);
                mma_f16(sacc[n1][0], sacc[n1][1], sacc[n1][2], sacc[n1][3],
                        qf[ks][0], qf[ks][1], qf[ks][2], qf[ks][3], kl2, kl3);
            }
        }

        // ---- mask + exp + row-sum + pack P (single fp16) ----
        uint32_t pp[16][2];
#pragma unroll
        for (int nt = 0; nt < 16; nt++) {
            int jj0 = nt * 8 + jj_b, jj1 = jj0 + 1;
            float p0 = __expf(sacc[nt][0] * 0.125f);
            float p1 = __expf(sacc[nt][1] * 0.125f);
            float p2 = __expf(sacc[nt][2] * 0.125f);
            float p3 = __expf(sacc[nt][3] * 0.125f);
            if (ch == 0) {
                if (jj0 < i_lo) p0 = 0.f;
                if (jj1 < i_lo) p1 = 0.f;
                if (jj0 < i_hi) p2 = 0.f;
                if (jj1 < i_hi) p3 = 0.f;
            } else if (ch == 2) {
                if (jj0 > i_lo) p0 = 0.f;
                if (jj1 > i_lo) p1 = 0.f;
                if (jj0 > i_hi) p2 = 0.f;
                if (jj1 > i_hi) p3 = 0.f;
            }
            ls0 += p0 + p1;
            ls1 += p2 + p3;
            pp[nt][0] = f16x2_of(p0, p1);
            pp[nt][1] = f16x2_of(p2, p3);
        }

        // ---- O += P (Vhi + Vlo) : 2 passes ----
#pragma unroll
        for (int ks = 0; ks < 8; ks++) {
            uint32_t a0 = pp[2 * ks][0], a1 = pp[2 * ks][1];
            uint32_t a2 = pp[2 * ks + 1][0], a3 = pp[2 * ks + 1][1];
#pragma unroll
            for (int ng = 0; ng < 4; ng++) {
                uint32_t vh0, vh1, vh2, vh3, vl0, vl1, vl2, vl3;
                uint32_t ad = sb + OFF_VH + (ks * 16 + v_kr) * AT_STR + (ng * 16 + v_nc) * 2;
                ldm_x4_t(vh0, vh1, vh2, vh3, ad);
                ldm_x4_t(vl0, vl1, vl2, vl3, ad + (OFF_VL - OFF_VH));
                int d0 = ng * 2, d1 = ng * 2 + 1;
                mma_f16(o[d0][0], o[d0][1], o[d0][2], o[d0][3], a0, a1, a2, a3, vh0, vh1);
                mma_f16(o[d1][0], o[d1][1], o[d1][2], o[d1][3], a0, a1, a2, a3, vh2, vh3);
                mma_f16(o[d0][0], o[d0][1], o[d0][2], o[d0][3], a0, a1, a2, a3, vl0, vl1);
                mma_f16(o[d1][0], o[d1][1], o[d1][2], o[d1][3], a0, a1, a2, a3, vl2, vl3);
            }
        }
    }

    // ---- finalize ----
    ls0 += __shfl_xor_sync(0xffffffffu, ls0, 1);
    ls0 += __shfl_xor_sync(0xffffffffu, ls0, 2);
    ls1 += __shfl_xor_sync(0xffffffffu, ls1, 1);
    ls1 += __shfl_xor_sync(0xffffffffu, ls1, 2);
    float inv0 = 1.f / ls0, inv1 = 1.f / ls1;

    const int qg0 = qt * QT + i_lo;
#pragma unroll
    for (int dt = 0; dt < 8; dt++) {
        int d = h * HDq + dt * 8 + jj_b;
        size_t base0 = (size_t)(b * Lq + qg0) * Dq + d;
        size_t base1 = base0 + (size_t)8 * Dq;
        *(uint32_t*)(oh_g + base0) = pack2(f16_of(o[dt][0] * inv0), f16_of(o[dt][1] * inv0));
        *(uint32_t*)(oh_g + base1) = pack2(f16_of(o[dt][2] * inv1), f16_of(o[dt][3] * inv1));
    }
}

// ---------------------------------------------------------------------------
extern "C" void kernel_launch(void* const* d_in, const int* in_sizes, int n_in,
                              void* d_out, int out_size)
{
    const float* x     = (const float*)d_in[0];
    const float* w_qkv = (const float*)d_in[1];
    const float* b_qkv = (const float*)d_in[2];
    const float* w_out = (const float*)d_in[3];
    const float* b_out = (const float*)d_in[4];
    float* out = (float*)d_out;

    __half *qkvh, *qkvl, *xh, *whi, *wlo, *ohi, *olo, *ah;
    cudaGetSymbolAddress((void**)&qkvh, g_qkvh);
    cudaGetSymbolAddress((void**)&qkvl, g_qkvl);
    cudaGetSymbolAddress((void**)&xh,  g_x_h);
    cudaGetSymbolAddress((void**)&whi, g_wqkv_hi);
    cudaGetSymbolAddress((void**)&wlo, g_wqkv_lo);
    cudaGetSymbolAddress((void**)&ohi, g_wout_hi);
    cudaGetSymbolAddress((void**)&olo, g_wout_lo);
    cudaGetSymbolAddress((void**)&ah,  g_attn_h);

    const int M = Bq * Lq;    // 4096

    cudaFuncSetAttribute(gemm_f16x2<true>,  cudaFuncAttributeMaxDynamicSharedMemorySize, SMEM_GEMM_BYTES);
    cudaFuncSetAttribute(gemm_f16x2<false>, cudaFuncAttributeMaxDynamicSharedMemorySize, SMEM_GEMM_BYTES);
    cudaFuncSetAttribute(attn_flash, cudaFuncAttributeMaxDynamicSharedMemorySize, SMEM_ATT);

    // 0) conversions: x -> fp16 single; weights -> fp16 hi/lo
    conv_fp16<<<(M * Dq) / 1024, 256>>>(x, xh, M * Dq);
    split_fp16<<<(Dq * 3 * Dq) / 1024, 256>>>(w_qkv, whi, wlo, Dq * 3 * Dq);
    split_fp16<<<(Dq * Dq) / 1024, 256>>>(w_out, ohi, olo, Dq * Dq);

    // 1) QKV projection -> fp16 hi/lo planes
    {
        dim3 grid(3 * Dq / 128, M / 128);   // 24 x 32
        gemm_f16x2<true><<<grid, 256, SMEM_GEMM_BYTES>>>(
            xh, whi, wlo, b_qkv, nullptr, qkvh, qkvl, M, 3 * Dq, Dq);
    }

    // 2) fp16 tensor-core windowed attention -> single fp16 plane
    {
        dim3 grid(Lq / QT, Hq, Bq);
        attn_flash<<<grid, 256, SMEM_ATT>>>(qkvh, qkvl, ah);
    }

    // 3) Output projection -> fp32 out
    {
        dim3 grid(Dq / 128, M / 128);       // 8 x 32
        gemm_f16x2<false><<<grid, 256, SMEM_GEMM_BYTES>>>(
            ah, ohi, olo, b_out, out, nullptr, nullptr, M, Dq, Dq);
    }
}

// round 13
// speedup vs baseline: 2.0294x; 1.4350x over previous
#include <cuda_runtime.h>
#include <cuda_fp16.h>
#include <cstdint>
#include <math.h>

#define Bq 2
#define Lq 2048
#define Dq 1024
#define Hq 16
#define HDq 64
#define HALFW 128
#define QT 128

// Scratch (no cudaMalloc allowed)
__device__ __half g_qkv16[(size_t)Bq * Lq * 3 * Dq];  // [B,L,3,D] single fp16
__device__ __half g_x_h[(size_t)Bq * Lq * Dq];
__device__ __half g_wqkv_h[(size_t)Dq * 3 * Dq];
__device__ __half g_wout_h[(size_t)Dq * Dq];
__device__ __half g_attn_h[(size_t)Bq * Lq * Dq];

// ===========================================================================
// helpers
// ===========================================================================
__device__ __forceinline__ uint16_t f16_of(float x) {
    return __half_raw(__float2half_rn(x)).x;
}

__device__ __forceinline__ uint32_t pack2(uint16_t a, uint16_t b) {
    return (uint32_t)a | ((uint32_t)b << 16);
}

__device__ __forceinline__ uint32_t f16x2_of(float flo, float fhi) {
    uint32_t r;
    asm("cvt.rn.f16x2.f32 %0, %1, %2;" : "=r"(r) : "f"(fhi), "f"(flo));
    return r;
}

__device__ __forceinline__ uint32_t smem_u32(const void* p) {
    uint32_t a;
    asm("{ .reg .u64 t; cvta.to.shared.u64 t, %1; cvt.u32.u64 %0, t; }" : "=r"(a) : "l"(p));
    return a;
}

__device__ __forceinline__ void ldm_x4(uint32_t& r0, uint32_t& r1, uint32_t& r2, uint32_t& r3,
                                       uint32_t addr) {
    asm volatile("ldmatrix.sync.aligned.m8n8.x4.shared.b16 {%0,%1,%2,%3}, [%4];"
                 : "=r"(r0), "=r"(r1), "=r"(r2), "=r"(r3) : "r"(addr));
}
__device__ __forceinline__ void ldm_x4_t(uint32_t& r0, uint32_t& r1, uint32_t& r2, uint32_t& r3,
                                         uint32_t addr) {
    asm volatile("ldmatrix.sync.aligned.m8n8.x4.trans.shared.b16 {%0,%1,%2,%3}, [%4];"
                 : "=r"(r0), "=r"(r1), "=r"(r2), "=r"(r3) : "r"(addr));
}

__device__ __forceinline__ void mma_f16(float& d0, float& d1, float& d2, float& d3,
                                        uint32_t a0, uint32_t a1, uint32_t a2, uint32_t a3,
                                        uint32_t b0, uint32_t b1) {
    asm volatile(
        "mma.sync.aligned.m16n8k16.row.col.f32.f16.f16.f32 "
        "{%0,%1,%2,%3}, {%4,%5,%6,%7}, {%8,%9}, {%0,%1,%2,%3};"
        : "+f"(d0), "+f"(d1), "+f"(d2), "+f"(d3)
        : "r"(a0), "r"(a1), "r"(a2), "r"(a3), "r"(b0), "r"(b1));
}

// ===========================================================================
// conversion kernel: fp32 -> fp16
// ===========================================================================
__global__ void __launch_bounds__(256)
conv_fp16(const float* __restrict__ in, __half* __restrict__ out, int n)
{
    int i = (blockIdx.x * 256 + threadIdx.x) * 4;
    if (i >= n) return;
    float4 v = *(const float4*)(in + i);
    *(uint2*)(out + i) = make_uint2(pack2(f16_of(v.x), f16_of(v.y)),
                                    pack2(f16_of(v.z), f16_of(v.w)));
}

// ===========================================================================
// fp16 single-precision GEMM (1 mma pass). CTA 128x128, warp 64x32 (2x4),
// K-chunk 32, double buffered, register prefetch. Epilogue fp16 or fp32.
// ===========================================================================
#define A_STRIDE 40          // fp16 elems per A row (80 B)
#define B_STRIDE 136         // fp16 elems per B row (272 B)
#define A_PLANE  (128 * A_STRIDE * 2)     // 10240 B
#define B_PLANE  (32 * B_STRIDE * 2)      // 8704 B
#define OFF_A    0
#define OFF_B    (A_PLANE)
#define BUF_BYTES (A_PLANE + B_PLANE)      // 18944
#define SMEM_GEMM_BYTES (2 * BUF_BYTES)    // 37888

template<bool OUT_F16>
__global__ void __launch_bounds__(256, 1)
gemm_f16(const __half* __restrict__ Ah, const __half* __restrict__ Bh,
         const float* __restrict__ bias, float* __restrict__ C,
         __half* __restrict__ C16, int M, int N, int K)
{
    extern __shared__ char smem[];
    const uint32_t sbase = smem_u32(smem);
    const int t    = threadIdx.x;
    const int lane = t & 31;
    const int wid  = t >> 5;
    const int warp_m = wid >> 2;
    const int warp_n = wid & 3;

    const int n0 = blockIdx.x * 128;
    const int m0 = blockIdx.y * 128;

    float acc[4][4][4];
#pragma unroll
    for (int i = 0; i < 4; i++)
#pragma unroll
        for (int j = 0; j < 4; j++)
#pragma unroll
            for (int r = 0; r < 4; r++) acc[i][j][r] = 0.f;

    const int a_m0 = t >> 2, a_g = t & 3;
    const int b_k0 = t >> 4, b_ng = t & 15;

    uint4 pa[2], pb[2];
#pragma unroll
    for (int p = 0; p < 2; p++) {
        int m = a_m0 + p * 64;
        pa[p] = *(const uint4*)(Ah + (size_t)(m0 + m) * K + a_g * 8);
        int k = b_k0 + p * 16;
        pb[p] = *(const uint4*)(Bh + (size_t)k * N + n0 + b_ng * 8);
    }

    const int NCH = K / 32;
    for (int c = 0; c < NCH; c++) {
        const uint32_t buf = sbase + (c & 1) * BUF_BYTES;

#pragma unroll
        for (int p = 0; p < 2; p++) {
            int m = a_m0 + p * 64;
            uint32_t aaddr = buf + OFF_A + m * (A_STRIDE * 2) + a_g * 16;
            asm volatile("st.shared.v4.b32 [%0], {%1,%2,%3,%4};" ::
                "r"(aaddr), "r"(pa[p].x), "r"(pa[p].y), "r"(pa[p].z), "r"(pa[p].w) : "memory");
            int k = b_k0 + p * 16;
            uint32_t baddr = buf + OFF_B + k * (B_STRIDE * 2) + b_ng * 16;
            asm volatile("st.shared.v4.b32 [%0], {%1,%2,%3,%4};" ::
                "r"(baddr), "r"(pb[p].x), "r"(pb[p].y), "r"(pb[p].z), "r"(pb[p].w) : "memory");
        }
        __syncthreads();

        if (c + 1 < NCH) {
            int k0n = (c + 1) * 32;
#pragma unroll
            for (int p = 0; p < 2; p++) {
                int m = a_m0 + p * 64;
                pa[p] = *(const uint4*)(Ah + (size_t)(m0 + m) * K + k0n + a_g * 8);
                int k = b_k0 + p * 16;
                pb[p] = *(const uint4*)(Bh + (size_t)(k0n + k) * N + n0 + b_ng * 8);
            }
        }

#pragma unroll
        for (int kk = 0; kk < 2; kk++) {
            const int a_row = (lane & 15);
            const int a_cb  = (lane >> 4);
            const int b_kr  = kk * 16 + (lane & 15);
            const int b_nc  = (lane & 16) ? 8 : 0;

            uint32_t af[4][4], bf[2][4];
#pragma unroll
            for (int mt = 0; mt < 4; mt++) {
                int row = warp_m * 64 + mt * 16 + a_row;
                uint32_t ad = buf + OFF_A + (row * A_STRIDE + kk * 16 + a_cb * 8) * 2;
                ldm_x4(af[mt][0], af[mt][1], af[mt][2], af[mt][3], ad);
            }
#pragma unroll
            for (int nb = 0; nb < 2; nb++) {
                int ncol = warp_n * 32 + nb * 16 + b_nc;
                uint32_t bd = buf + OFF_B + (b_kr * B_STRIDE + ncol) * 2;
                ldm_x4_t(bf[nb][0], bf[nb][1], bf[nb][2], bf[nb][3], bd);
            }
#pragma unroll
            for (int mt = 0; mt < 4; mt++)
#pragma unroll
                for (int nt = 0; nt < 4; nt++) {
                    int nb = nt >> 1, half = nt & 1;
                    mma_f16(acc[mt][nt][0], acc[mt][nt][1], acc[mt][nt][2], acc[mt][nt][3],
                            af[mt][0], af[mt][1], af[mt][2], af[mt][3],
                            bf[nb][half * 2], bf[nb][half * 2 + 1]);
                }
        }
    }

    const int r_base = m0 + warp_m * 64 + (lane >> 2);
    const int c_base = n0 + warp_n * 32 + 2 * (lane & 3);
#pragma unroll
    for (int mt = 0; mt < 4; mt++) {
#pragma unroll
        for (int nt = 0; nt < 4; nt++) {
            int col = c_base + nt * 8;
            float b0 = bias[col], b1 = bias[col + 1];
            int r0 = r_base + mt * 16;
            float v00 = acc[mt][nt][0] + b0, v01 = acc[mt][nt][1] + b1;
            float v10 = acc[mt][nt][2] + b0, v11 = acc[mt][nt][3] + b1;
            if (OUT_F16) {
                *(uint32_t*)(C16 + (size_t)r0 * N + col)       = pack2(f16_of(v00), f16_of(v01));
                *(uint32_t*)(C16 + (size_t)(r0 + 8) * N + col) = pack2(f16_of(v10), f16_of(v11));
            } else {
                *(float2*)(C + (size_t)r0 * N + col)       = make_float2(v00, v01);
                *(float2*)(C + (size_t)(r0 + 8) * N + col) = make_float2(v10, v11);
            }
        }
    }
}

// ===========================================================================
// fp16 tensor-core windowed flash attention — all operands single fp16.
// S = Q K^T (1 pass); P = exp(S/8) fp16; O += P V (1 pass).
// Masks/layout identical to the passing lineage.
// ===========================================================================
#define AT_STR 144
#define OFF_K 0
#define OFF_V 18432
#define SMEM_ATT 36864

__global__ void __launch_bounds__(256, 1)
attn_flash(const __half* __restrict__ qkv, __half* __restrict__ oh_g)
{
    extern __shared__ char smem[];
    const uint32_t sb = smem_u32(smem);
    const int qt = blockIdx.x, h = blockIdx.y, b = blockIdx.z;
    const int t = threadIdx.x, lane = t & 31, wid = t >> 5;

    // ---- stage Q tile into K region, grab A-frags ----
#pragma unroll
    for (int p = 0; p < 4; p++) {
        int idx = t + p * 256;
        int row = idx >> 3, g = idx & 7;
        const __half* src = qkv
            + ((size_t)(b * Lq + qt * QT + row) * 3 + 0) * Dq + h * HDq + g * 8;
        uint4 v = *(const uint4*)src;
        uint32_t dst = sb + OFF_K + row * AT_STR + g * 16;
        asm volatile("st.shared.v4.b32 [%0], {%1,%2,%3,%4};" ::
                     "r"(dst), "r"(v.x), "r"(v.y), "r"(v.z), "r"(v.w) : "memory");
    }
    __syncthreads();

    uint32_t qf[4][4];
    {
        int a_row = lane & 15, a_cb = lane >> 4;
        int qrow = wid * 16 + a_row;
#pragma unroll
        for (int ks = 0; ks < 4; ks++) {
            uint32_t ad = sb + OFF_K + qrow * AT_STR + (ks * 16 + a_cb * 8) * 2;
            ldm_x4(qf[ks][0], qf[ks][1], qf[ks][2], qf[ks][3], ad);
        }
    }

    float o[8][4];
#pragma unroll
    for (int i = 0; i < 8; i++)
#pragma unroll
        for (int r = 0; r < 4; r++) o[i][r] = 0.f;
    float ls0 = 0.f, ls1 = 0.f;

    const int i_lo = wid * 16 + (lane >> 2);
    const int i_hi = i_lo + 8;
    const int jj_b = (lane & 3) * 2;

    const int bn_row = (lane & 7) + ((lane & 16) >> 1);
    const int bk_off = (lane & 8);
    const int v_kr = (lane & 15);
    const int v_nc = (lane & 16) ? 8 : 0;

    for (int ch = 0; ch < 3; ch++) {
        if (ch == 0 && qt == 0) continue;
        if (ch == 2 && qt == (Lq / QT) - 1) continue;
        const int jbase = qt * QT + (ch - 1) * 128;

        __syncthreads();
#pragma unroll
        for (int p = 0; p < 8; p++) {
            int idx = t + p * 256;
            int plane = idx >> 10, rem = idx & 1023, row = rem >> 3, g = rem & 7;
            int which = plane + 1;     // 1 = K, 2 = V
            const __half* src = qkv
                + ((size_t)(b * Lq + jbase + row) * 3 + which) * Dq + h * HDq + g * 8;
            uint4 v = *(const uint4*)src;
            uint32_t off = plane ? OFF_V : OFF_K;
            uint32_t dst = sb + off + row * AT_STR + g * 16;
            asm volatile("st.shared.v4.b32 [%0], {%1,%2,%3,%4};" ::
                         "r"(dst), "r"(v.x), "r"(v.y), "r"(v.z), "r"(v.w) : "memory");
        }
        __syncthreads();

        // ---- S = Q K^T (1 pass) ----
        float sacc[16][4];
#pragma unroll
        for (int i = 0; i < 16; i++)
#pragma unroll
            for (int r = 0; r < 4; r++) sacc[i][r] = 0.f;

#pragma unroll
        for (int ks = 0; ks < 4; ks++) {
#pragma unroll
            for (int ng = 0; ng < 8; ng++) {
                uint32_t k0, k1, k2, k3;
                uint32_t ad = sb + OFF_K + (ng * 16 + bn_row) * AT_STR + (ks * 16 + bk_off) * 2;
                ldm_x4(k0, k1, k2, k3, ad);
                int n0 = ng * 2, n1 = ng * 2 + 1;
                mma_f16(sacc[n0][0], sacc[n0][1], sacc[n0][2], sacc[n0][3],
                        qf[ks][0], qf[ks][1], qf[ks][2], qf[ks][3], k0, k1);
                mma_f16(sacc[n1][0], sacc[n1][1], sacc[n1][2], sacc[n1][3],
                        qf[ks][0], qf[ks][1], qf[ks][2], qf[ks][3], k2, k3);
            }
        }

        // ---- mask + exp + row-sum + pack P ----
        uint32_t pp[16][2];
#pragma unroll
        for (int nt = 0; nt < 16; nt++) {
            int jj0 = nt * 8 + jj_b, jj1 = jj0 + 1;
            float p0 = __expf(sacc[nt][0] * 0.125f);
            float p1 = __expf(sacc[nt][1] * 0.125f);
            float p2 = __expf(sacc[nt][2] * 0.125f);
            float p3 = __expf(sacc[nt][3] * 0.125f);
            if (ch == 0) {
                if (jj0 < i_lo) p0 = 0.f;
                if (jj1 < i_lo) p1 = 0.f;
                if (jj0 < i_hi) p2 = 0.f;
                if (jj1 < i_hi) p3 = 0.f;
            } else if (ch == 2) {
                if (jj0 > i_lo) p0 = 0.f;
                if (jj1 > i_lo) p1 = 0.f;
                if (jj0 > i_hi) p2 = 0.f;
                if (jj1 > i_hi) p3 = 0.f;
            }
            ls0 += p0 + p1;
            ls1 += p2 + p3;
            pp[nt][0] = f16x2_of(p0, p1);
            pp[nt][1] = f16x2_of(p2, p3);
        }

        // ---- O += P V (1 pass) ----
#pragma unroll
        for (int ks = 0; ks < 8; ks++) {
            uint32_t a0 = pp[2 * ks][0], a1 = pp[2 * ks][1];
            uint32_t a2 = pp[2 * ks + 1][0], a3 = pp[2 * ks + 1][1];
#pragma unroll
            for (int ng = 0; ng < 4; ng++) {
                uint32_t v0, v1, v2, v3;
                uint32_t ad = sb + OFF_V + (ks * 16 + v_kr) * AT_STR + (ng * 16 + v_nc) * 2;
                ldm_x4_t(v0, v1, v2, v3, ad);
                int d0 = ng * 2, d1 = ng * 2 + 1;
                mma_f16(o[d0][0], o[d0][1], o[d0][2], o[d0][3], a0, a1, a2, a3, v0, v1);
                mma_f16(o[d1][0], o[d1][1], o[d1][2], o[d1][3], a0, a1, a2, a3, v2, v3);
            }
        }
    }

    // ---- finalize ----
    ls0 += __shfl_xor_sync(0xffffffffu, ls0, 1);
    ls0 += __shfl_xor_sync(0xffffffffu, ls0, 2);
    ls1 += __shfl_xor_sync(0xffffffffu, ls1, 1);
    ls1 += __shfl_xor_sync(0xffffffffu, ls1, 2);
    float inv0 = 1.f / ls0, inv1 = 1.f / ls1;

    const int qg0 = qt * QT + i_lo;
#pragma unroll
    for (int dt = 0; dt < 8; dt++) {
        int d = h * HDq + dt * 8 + jj_b;
        size_t base0 = (size_t)(b * Lq + qg0) * Dq + d;
        size_t base1 = base0 + (size_t)8 * Dq;
        *(uint32_t*)(oh_g + base0) = pack2(f16_of(o[dt][0] * inv0), f16_of(o[dt][1] * inv0));
        *(uint32_t*)(oh_g + base1) = pack2(f16_of(o[dt][2] * inv1), f16_of(o[dt][3] * inv1));
    }
}

// ---------------------------------------------------------------------------
extern "C" void kernel_launch(void* const* d_in, const int* in_sizes, int n_in,
                              void* d_out, int out_size)
{
    const float* x     = (const float*)d_in[0];
    const float* w_qkv = (const float*)d_in[1];
    const float* b_qkv = (const float*)d_in[2];
    const float* w_out = (const float*)d_in[3];
    const float* b_out = (const float*)d_in[4];
    float* out = (float*)d_out;

    __half *qkv16, *xh, *wh, *oh, *ah;
    cudaGetSymbolAddress((void**)&qkv16, g_qkv16);
    cudaGetSymbolAddress((void**)&xh, g_x_h);
    cudaGetSymbolAddress((void**)&wh, g_wqkv_h);
    cudaGetSymbolAddress((void**)&oh, g_wout_h);
    cudaGetSymbolAddress((void**)&ah, g_attn_h);

    const int M = Bq * Lq;    // 4096

    cudaFuncSetAttribute(gemm_f16<true>,  cudaFuncAttributeMaxDynamicSharedMemorySize, SMEM_GEMM_BYTES);
    cudaFuncSetAttribute(gemm_f16<false>, cudaFuncAttributeMaxDynamicSharedMemorySize, SMEM_GEMM_BYTES);
    cudaFuncSetAttribute(attn_flash, cudaFuncAttributeMaxDynamicSharedMemorySize, SMEM_ATT);

    // 0) conversions to fp16
    conv_fp16<<<(M * Dq) / 1024, 256>>>(x, xh, M * Dq);
    conv_fp16<<<(Dq * 3 * Dq) / 1024, 256>>>(w_qkv, wh, Dq * 3 * Dq);
    conv_fp16<<<(Dq * Dq) / 1024, 256>>>(w_out, oh, Dq * Dq);

    // 1) QKV projection -> single fp16 plane
    {
        dim3 grid(3 * Dq / 128, M / 128);   // 24 x 32
        gemm_f16<true><<<grid, 256, SMEM_GEMM_BYTES>>>(
            xh, wh, b_qkv, nullptr, qkv16, M, 3 * Dq, Dq);
    }

    // 2) fp16 tensor-core windowed attention
    {
        dim3 grid(Lq / QT, Hq, Bq);
        attn_flash<<<grid, 256, SMEM_ATT>>>(qkv16, ah);
    }

    // 3) Output projection -> fp32 out
    {
        dim3 grid(Dq / 128, M / 128);       // 8 x 32
        gemm_f16<false><<<grid, 256, SMEM_GEMM_BYTES>>>(
            ah, oh, b_out, out, nullptr, M, Dq, Dq);
    }
}

// round 14
// speedup vs baseline: 2.2466x; 1.1070x over previous
#include <cuda_runtime.h>
#include <cuda_fp16.h>
#include <cstdint>
#include <math.h>

#define Bq 2
#define Lq 2048
#define Dq 1024
#define Hq 16
#define HDq 64
#define HALFW 128
#define QT 128

// Scratch (no cudaMalloc allowed)
__device__ __half g_qkv16[(size_t)Bq * Lq * 3 * Dq];  // [B,L,3,D] single fp16
__device__ __half g_x_h[(size_t)Bq * Lq * Dq];
__device__ __half g_wqkv_h[(size_t)Dq * 3 * Dq];
__device__ __half g_wout_h[(size_t)Dq * Dq];
__device__ __half g_attn_h[(size_t)Bq * Lq * Dq];

// ===========================================================================
// helpers
// ===========================================================================
__device__ __forceinline__ uint16_t f16_of(float x) {
    return __half_raw(__float2half_rn(x)).x;
}

__device__ __forceinline__ uint32_t pack2(uint16_t a, uint16_t b) {
    return (uint32_t)a | ((uint32_t)b << 16);
}

__device__ __forceinline__ uint32_t f16x2_of(float flo, float fhi) {
    uint32_t r;
    asm("cvt.rn.f16x2.f32 %0, %1, %2;" : "=r"(r) : "f"(fhi), "f"(flo));
    return r;
}

__device__ __forceinline__ uint32_t smem_u32(const void* p) {
    uint32_t a;
    asm("{ .reg .u64 t; cvta.to.shared.u64 t, %1; cvt.u32.u64 %0, t; }" : "=r"(a) : "l"(p));
    return a;
}

__device__ __forceinline__ void ldm_x4(uint32_t& r0, uint32_t& r1, uint32_t& r2, uint32_t& r3,
                                       uint32_t addr) {
    asm volatile("ldmatrix.sync.aligned.m8n8.x4.shared.b16 {%0,%1,%2,%3}, [%4];"
                 : "=r"(r0), "=r"(r1), "=r"(r2), "=r"(r3) : "r"(addr));
}
__device__ __forceinline__ void ldm_x4_t(uint32_t& r0, uint32_t& r1, uint32_t& r2, uint32_t& r3,
                                         uint32_t addr) {
    asm volatile("ldmatrix.sync.aligned.m8n8.x4.trans.shared.b16 {%0,%1,%2,%3}, [%4];"
                 : "=r"(r0), "=r"(r1), "=r"(r2), "=r"(r3) : "r"(addr));
}

__device__ __forceinline__ void mma_f16(float& d0, float& d1, float& d2, float& d3,
                                        uint32_t a0, uint32_t a1, uint32_t a2, uint32_t a3,
                                        uint32_t b0, uint32_t b1) {
    asm volatile(
        "mma.sync.aligned.m16n8k16.row.col.f32.f16.f16.f32 "
        "{%0,%1,%2,%3}, {%4,%5,%6,%7}, {%8,%9}, {%0,%1,%2,%3};"
        : "+f"(d0), "+f"(d1), "+f"(d2), "+f"(d3)
        : "r"(a0), "r"(a1), "r"(a2), "r"(a3), "r"(b0), "r"(b1));
}

// ===========================================================================
// conversion kernel: fp32 -> fp16
// ===========================================================================
__global__ void __launch_bounds__(256)
conv_fp16(const float* __restrict__ in, __half* __restrict__ out, int n)
{
    int i = (blockIdx.x * 256 + threadIdx.x) * 4;
    if (i >= n) return;
    float4 v = *(const float4*)(in + i);
    *(uint2*)(out + i) = make_uint2(pack2(f16_of(v.x), f16_of(v.y)),
                                    pack2(f16_of(v.z), f16_of(v.w)));
}

// ===========================================================================
// fp16 GEMM (1 mma pass). CTA 128x128, warp 64x32 (2x4).
// K-chunk 64 (amortize per-chunk overhead), double buffered, reg prefetch.
// ===========================================================================
#define A_STRIDE 72          // fp16 elems per A row (144 B; 64 data + 8 pad)
#define B_STRIDE 136         // fp16 elems per B row (272 B)
#define A_PLANE  (128 * A_STRIDE * 2)     // 18432 B
#define B_PLANE  (64 * B_STRIDE * 2)      // 17408 B
#define OFF_A    0
#define OFF_B    (A_PLANE)
#define BUF_BYTES (A_PLANE + B_PLANE)      // 35840
#define SMEM_GEMM_BYTES (2 * BUF_BYTES)    // 71680

template<bool OUT_F16>
__global__ void __launch_bounds__(256, 1)
gemm_f16(const __half* __restrict__ Ah, const __half* __restrict__ Bh,
         const float* __restrict__ bias, float* __restrict__ C,
         __half* __restrict__ C16, int M, int N, int K)
{
    extern __shared__ char smem[];
    const uint32_t sbase = smem_u32(smem);
    const int t    = threadIdx.x;
    const int lane = t & 31;
    const int wid  = t >> 5;
    const int warp_m = wid >> 2;
    const int warp_n = wid & 3;

    const int n0 = blockIdx.x * 128;
    const int m0 = blockIdx.y * 128;

    float acc[4][4][4];
#pragma unroll
    for (int i = 0; i < 4; i++)
#pragma unroll
        for (int j = 0; j < 4; j++)
#pragma unroll
            for (int r = 0; r < 4; r++) acc[i][j][r] = 0.f;

    // loaders: A 128x64 (row=idx>>3, g=idx&7); B 64x128 (k=idx>>4, ng=idx&15)
    const int a_m0 = t >> 3, a_g = t & 7;
    const int b_k0 = t >> 4, b_ng = t & 15;

    uint4 pa[4], pb[4];
#pragma unroll
    for (int p = 0; p < 4; p++) {
        int m = a_m0 + p * 32;
        pa[p] = *(const uint4*)(Ah + (size_t)(m0 + m) * K + a_g * 8);
        int k = b_k0 + p * 16;
        pb[p] = *(const uint4*)(Bh + (size_t)k * N + n0 + b_ng * 8);
    }

    const int NCH = K / 64;
    for (int c = 0; c < NCH; c++) {
        const uint32_t buf = sbase + (c & 1) * BUF_BYTES;

#pragma unroll
        for (int p = 0; p < 4; p++) {
            int m = a_m0 + p * 32;
            uint32_t aaddr = buf + OFF_A + m * (A_STRIDE * 2) + a_g * 16;
            asm volatile("st.shared.v4.b32 [%0], {%1,%2,%3,%4};" ::
                "r"(aaddr), "r"(pa[p].x), "r"(pa[p].y), "r"(pa[p].z), "r"(pa[p].w) : "memory");
            int k = b_k0 + p * 16;
            uint32_t baddr = buf + OFF_B + k * (B_STRIDE * 2) + b_ng * 16;
            asm volatile("st.shared.v4.b32 [%0], {%1,%2,%3,%4};" ::
                "r"(baddr), "r"(pb[p].x), "r"(pb[p].y), "r"(pb[p].z), "r"(pb[p].w) : "memory");
        }
        __syncthreads();

        if (c + 1 < NCH) {
            int k0n = (c + 1) * 64;
#pragma unroll
            for (int p = 0; p < 4; p++) {
                int m = a_m0 + p * 32;
                pa[p] = *(const uint4*)(Ah + (size_t)(m0 + m) * K + k0n + a_g * 8);
                int k = b_k0 + p * 16;
                pb[p] = *(const uint4*)(Bh + (size_t)(k0n + k) * N + n0 + b_ng * 8);
            }
        }

#pragma unroll
        for (int kk = 0; kk < 4; kk++) {
            const int a_row = (lane & 15);
            const int a_cb  = (lane >> 4);
            const int b_kr  = kk * 16 + (lane & 15);
            const int b_nc  = (lane & 16) ? 8 : 0;

            uint32_t af[4][4], bf[2][4];
#pragma unroll
            for (int mt = 0; mt < 4; mt++) {
                int row = warp_m * 64 + mt * 16 + a_row;
                uint32_t ad = buf + OFF_A + (row * A_STRIDE + kk * 16 + a_cb * 8) * 2;
                ldm_x4(af[mt][0], af[mt][1], af[mt][2], af[mt][3], ad);
            }
#pragma unroll
            for (int nb = 0; nb < 2; nb++) {
                int ncol = warp_n * 32 + nb * 16 + b_nc;
                uint32_t bd = buf + OFF_B + (b_kr * B_STRIDE + ncol) * 2;
                ldm_x4_t(bf[nb][0], bf[nb][1], bf[nb][2], bf[nb][3], bd);
            }
#pragma unroll
            for (int mt = 0; mt < 4; mt++)
#pragma unroll
                for (int nt = 0; nt < 4; nt++) {
                    int nb = nt >> 1, half = nt & 1;
                    mma_f16(acc[mt][nt][0], acc[mt][nt][1], acc[mt][nt][2], acc[mt][nt][3],
                            af[mt][0], af[mt][1], af[mt][2], af[mt][3],
                            bf[nb][half * 2], bf[nb][half * 2 + 1]);
                }
        }
    }

    const int r_base = m0 + warp_m * 64 + (lane >> 2);
    const int c_base = n0 + warp_n * 32 + 2 * (lane & 3);
#pragma unroll
    for (int mt = 0; mt < 4; mt++) {
#pragma unroll
        for (int nt = 0; nt < 4; nt++) {
            int col = c_base + nt * 8;
            float b0 = bias[col], b1 = bias[col + 1];
            int r0 = r_base + mt * 16;
            float v00 = acc[mt][nt][0] + b0, v01 = acc[mt][nt][1] + b1;
            float v10 = acc[mt][nt][2] + b0, v11 = acc[mt][nt][3] + b1;
            if (OUT_F16) {
                *(uint32_t*)(C16 + (size_t)r0 * N + col)       = pack2(f16_of(v00), f16_of(v01));
                *(uint32_t*)(C16 + (size_t)(r0 + 8) * N + col) = pack2(f16_of(v10), f16_of(v11));
            } else {
                *(float2*)(C + (size_t)r0 * N + col)       = make_float2(v00, v01);
                *(float2*)(C + (size_t)(r0 + 8) * N + col) = make_float2(v10, v11);
            }
        }
    }
}

// ===========================================================================
// fp16 tensor-core windowed flash attention (unchanged from round 13 — passing)
// ===========================================================================
#define AT_STR 144
#define OFF_K 0
#define OFF_V 18432
#define SMEM_ATT 36864

__global__ void __launch_bounds__(256, 1)
attn_flash(const __half* __restrict__ qkv, __half* __restrict__ oh_g)
{
    extern __shared__ char smem[];
    const uint32_t sb = smem_u32(smem);
    const int qt = blockIdx.x, h = blockIdx.y, b = blockIdx.z;
    const int t = threadIdx.x, lane = t & 31, wid = t >> 5;

#pragma unroll
    for (int p = 0; p < 4; p++) {
        int idx = t + p * 256;
        int row = idx >> 3, g = idx & 7;
        const __half* src = qkv
            + ((size_t)(b * Lq + qt * QT + row) * 3 + 0) * Dq + h * HDq + g * 8;
        uint4 v = *(const uint4*)src;
        uint32_t dst = sb + OFF_K + row * AT_STR + g * 16;
        asm volatile("st.shared.v4.b32 [%0], {%1,%2,%3,%4};" ::
                     "r"(dst), "r"(v.x), "r"(v.y), "r"(v.z), "r"(v.w) : "memory");
    }
    __syncthreads();

    uint32_t qf[4][4];
    {
        int a_row = lane & 15, a_cb = lane >> 4;
        int qrow = wid * 16 + a_row;
#pragma unroll
        for (int ks = 0; ks < 4; ks++) {
            uint32_t ad = sb + OFF_K + qrow * AT_STR + (ks * 16 + a_cb * 8) * 2;
            ldm_x4(qf[ks][0], qf[ks][1], qf[ks][2], qf[ks][3], ad);
        }
    }

    float o[8][4];
#pragma unroll
    for (int i = 0; i < 8; i++)
#pragma unroll
        for (int r = 0; r < 4; r++) o[i][r] = 0.f;
    float ls0 = 0.f, ls1 = 0.f;

    const int i_lo = wid * 16 + (lane >> 2);
    const int i_hi = i_lo + 8;
    const int jj_b = (lane & 3) * 2;

    const int bn_row = (lane & 7) + ((lane & 16) >> 1);
    const int bk_off = (lane & 8);
    const int v_kr = (lane & 15);
    const int v_nc = (lane & 16) ? 8 : 0;

    for (int ch = 0; ch < 3; ch++) {
        if (ch == 0 && qt == 0) continue;
        if (ch == 2 && qt == (Lq / QT) - 1) continue;
        const int jbase = qt * QT + (ch - 1) * 128;

        __syncthreads();
#pragma unroll
        for (int p = 0; p < 8; p++) {
            int idx = t + p * 256;
            int plane = idx >> 10, rem = idx & 1023, row = rem >> 3, g = rem & 7;
            int which = plane + 1;     // 1 = K, 2 = V
            const __half* src = qkv
                + ((size_t)(b * Lq + jbase + row) * 3 + which) * Dq + h * HDq + g * 8;
            uint4 v = *(const uint4*)src;
            uint32_t off = plane ? OFF_V : OFF_K;
            uint32_t dst = sb + off + row * AT_STR + g * 16;
            asm volatile("st.shared.v4.b32 [%0], {%1,%2,%3,%4};" ::
                         "r"(dst), "r"(v.x), "r"(v.y), "r"(v.z), "r"(v.w) : "memory");
        }
        __syncthreads();

        float sacc[16][4];
#pragma unroll
        for (int i = 0; i < 16; i++)
#pragma unroll
            for (int r = 0; r < 4; r++) sacc[i][r] = 0.f;

#pragma unroll
        for (int ks = 0; ks < 4; ks++) {
#pragma unroll
            for (int ng = 0; ng < 8; ng++) {
                uint32_t k0, k1, k2, k3;
                uint32_t ad = sb + OFF_K + (ng * 16 + bn_row) * AT_STR + (ks * 16 + bk_off) * 2;
                ldm_x4(k0, k1, k2, k3, ad);
                int n0 = ng * 2, n1 = ng * 2 + 1;
                mma_f16(sacc[n0][0], sacc[n0][1], sacc[n0][2], sacc[n0][3],
                        qf[ks][0], qf[ks][1], qf[ks][2], qf[ks][3], k0, k1);
                mma_f16(sacc[n1][0], sacc[n1][1], sacc[n1][2], sacc[n1][3],
                        qf[ks][0], qf[ks][1], qf[ks][2], qf[ks][3], k2, k3);
            }
        }

        uint32_t pp[16][2];
#pragma unroll
        for (int nt = 0; nt < 16; nt++) {
            int jj0 = nt * 8 + jj_b, jj1 = jj0 + 1;
            float p0 = __expf(sacc[nt][0] * 0.125f);
            float p1 = __expf(sacc[nt][1] * 0.125f);
            float p2 = __expf(sacc[nt][2] * 0.125f);
            float p3 = __expf(sacc[nt][3] * 0.125f);
            if (ch == 0) {
                if (jj0 < i_lo) p0 = 0.f;
                if (jj1 < i_lo) p1 = 0.f;
                if (jj0 < i_hi) p2 = 0.f;
                if (jj1 < i_hi) p3 = 0.f;
            } else if (ch == 2) {
                if (jj0 > i_lo) p0 = 0.f;
                if (jj1 > i_lo) p1 = 0.f;
                if (jj0 > i_hi) p2 = 0.f;
                if (jj1 > i_hi) p3 = 0.f;
            }
            ls0 += p0 + p1;
            ls1 += p2 + p3;
            pp[nt][0] = f16x2_of(p0, p1);
            pp[nt][1] = f16x2_of(p2, p3);
        }

#pragma unroll
        for (int ks = 0; ks < 8; ks++) {
            uint32_t a0 = pp[2 * ks][0], a1 = pp[2 * ks][1];
            uint32_t a2 = pp[2 * ks + 1][0], a3 = pp[2 * ks + 1][1];
#pragma unroll
            for (int ng = 0; ng < 4; ng++) {
                uint32_t v0, v1, v2, v3;
                uint32_t ad = sb + OFF_V + (ks * 16 + v_kr) * AT_STR + (ng * 16 + v_nc) * 2;
                ldm_x4_t(v0, v1, v2, v3, ad);
                int d0 = ng * 2, d1 = ng * 2 + 1;
                mma_f16(o[d0][0], o[d0][1], o[d0][2], o[d0][3], a0, a1, a2, a3, v0, v1);
                mma_f16(o[d1][0], o[d1][1], o[d1][2], o[d1][3], a0, a1, a2, a3, v2, v3);
            }
        }
    }

    ls0 += __shfl_xor_sync(0xffffffffu, ls0, 1);
    ls0 += __shfl_xor_sync(0xffffffffu, ls0, 2);
    ls1 += __shfl_xor_sync(0xffffffffu, ls1, 1);
    ls1 += __shfl_xor_sync(0xffffffffu, ls1, 2);
    float inv0 = 1.f / ls0, inv1 = 1.f / ls1;

    const int qg0 = qt * QT + i_lo;
#pragma unroll
    for (int dt = 0; dt < 8; dt++) {
        int d = h * HDq + dt * 8 + jj_b;
        size_t base0 = (size_t)(b * Lq + qg0) * Dq + d;
        size_t base1 = base0 + (size_t)8 * Dq;
        *(uint32_t*)(oh_g + base0) = pack2(f16_of(o[dt][0] * inv0), f16_of(o[dt][1] * inv0));
        *(uint32_t*)(oh_g + base1) = pack2(f16_of(o[dt][2] * inv1), f16_of(o[dt][3] * inv1));
    }
}

// ---------------------------------------------------------------------------
extern "C" void kernel_launch(void* const* d_in, const int* in_sizes, int n_in,
                              void* d_out, int out_size)
{
    const float* x     = (const float*)d_in[0];
    const float* w_qkv = (const float*)d_in[1];
    const float* b_qkv = (const float*)d_in[2];
    const float* w_out = (const float*)d_in[3];
    const float* b_out = (const float*)d_in[4];
    float* out = (float*)d_out;

    __half *qkv16, *xh, *wh, *oh, *ah;
    cudaGetSymbolAddress((void**)&qkv16, g_qkv16);
    cudaGetSymbolAddress((void**)&xh, g_x_h);
    cudaGetSymbolAddress((void**)&wh, g_wqkv_h);
    cudaGetSymbolAddress((void**)&oh, g_wout_h);
    cudaGetSymbolAddress((void**)&ah, g_attn_h);

    const int M = Bq * Lq;    // 4096

    cudaFuncSetAttribute(gemm_f16<true>,  cudaFuncAttributeMaxDynamicSharedMemorySize, SMEM_GEMM_BYTES);
    cudaFuncSetAttribute(gemm_f16<false>, cudaFuncAttributeMaxDynamicSharedMemorySize, SMEM_GEMM_BYTES);
    cudaFuncSetAttribute(attn_flash, cudaFuncAttributeMaxDynamicSharedMemorySize, SMEM_ATT);

    // 0) conversions to fp16
    conv_fp16<<<(M * Dq) / 1024, 256>>>(x, xh, M * Dq);
    conv_fp16<<<(Dq * 3 * Dq) / 1024, 256>>>(w_qkv, wh, Dq * 3 * Dq);
    conv_fp16<<<(Dq * Dq) / 1024, 256>>>(w_out, oh, Dq * Dq);

    // 1) QKV projection -> single fp16 plane
    {
        dim3 grid(3 * Dq / 128, M / 128);   // 24 x 32
        gemm_f16<true><<<grid, 256, SMEM_GEMM_BYTES>>>(
            xh, wh, b_qkv, nullptr, qkv16, M, 3 * Dq, Dq);
    }

    // 2) fp16 tensor-core windowed attention
    {
        dim3 grid(Lq / QT, Hq, Bq);
        attn_flash<<<grid, 256, SMEM_ATT>>>(qkv16, ah);
    }

    // 3) Output projection -> fp32 out
    {
        dim3 grid(Dq / 128, M / 128);       // 8 x 32
        gemm_f16<false><<<grid, 256, SMEM_GEMM_BYTES>>>(
            ah, oh, b_out, out, nullptr, M, Dq, Dq);
    }
}

// round 15
// speedup vs baseline: 2.3155x; 1.0307x over previous
#include <cuda_runtime.h>
#include <cuda_fp16.h>
#include <cstdint>
#include <math.h>

#define Bq 2
#define Lq 2048
#define Dq 1024
#define Hq 16
#define HDq 64
#define HALFW 128
#define QT 128

// Scratch (no cudaMalloc allowed)
__device__ __half g_qkv16[(size_t)Bq * Lq * 3 * Dq];  // [B,L,3,D] single fp16
__device__ __half g_x_h[(size_t)Bq * Lq * Dq];
__device__ __half g_wqkv_h[(size_t)Dq * 3 * Dq];
__device__ __half g_wout_h[(size_t)Dq * Dq];
__device__ __half g_attn_h[(size_t)Bq * Lq * Dq];

// ===========================================================================
// helpers
// ===========================================================================
__device__ __forceinline__ uint16_t f16_of(float x) {
    return __half_raw(__float2half_rn(x)).x;
}

__device__ __forceinline__ uint32_t pack2(uint16_t a, uint16_t b) {
    return (uint32_t)a | ((uint32_t)b << 16);
}

__device__ __forceinline__ uint32_t f16x2_of(float flo, float fhi) {
    uint32_t r;
    asm("cvt.rn.f16x2.f32 %0, %1, %2;" : "=r"(r) : "f"(fhi), "f"(flo));
    return r;
}

__device__ __forceinline__ uint32_t smem_u32(const void* p) {
    uint32_t a;
    asm("{ .reg .u64 t; cvta.to.shared.u64 t, %1; cvt.u32.u64 %0, t; }" : "=r"(a) : "l"(p));
    return a;
}

__device__ __forceinline__ void ldm_x4(uint32_t& r0, uint32_t& r1, uint32_t& r2, uint32_t& r3,
                                       uint32_t addr) {
    asm volatile("ldmatrix.sync.aligned.m8n8.x4.shared.b16 {%0,%1,%2,%3}, [%4];"
                 : "=r"(r0), "=r"(r1), "=r"(r2), "=r"(r3) : "r"(addr));
}
__device__ __forceinline__ void ldm_x4_t(uint32_t& r0, uint32_t& r1, uint32_t& r2, uint32_t& r3,
                                         uint32_t addr) {
    asm volatile("ldmatrix.sync.aligned.m8n8.x4.trans.shared.b16 {%0,%1,%2,%3}, [%4];"
                 : "=r"(r0), "=r"(r1), "=r"(r2), "=r"(r3) : "r"(addr));
}

__device__ __forceinline__ void mma_f16(float& d0, float& d1, float& d2, float& d3,
                                        uint32_t a0, uint32_t a1, uint32_t a2, uint32_t a3,
                                        uint32_t b0, uint32_t b1) {
    asm volatile(
        "mma.sync.aligned.m16n8k16.row.col.f32.f16.f16.f32 "
        "{%0,%1,%2,%3}, {%4,%5,%6,%7}, {%8,%9}, {%0,%1,%2,%3};"
        : "+f"(d0), "+f"(d1), "+f"(d2), "+f"(d3)
        : "r"(a0), "r"(a1), "r"(a2), "r"(a3), "r"(b0), "r"(b1));
}

__device__ __forceinline__ void cp16(uint32_t s, const void* g) {
    asm volatile("cp.async.cg.shared.global [%0], [%1], 16;" :: "r"(s), "l"(g) : "memory");
}
#define CP_COMMIT() asm volatile("cp.async.commit_group;" ::: "memory")
#define CP_WAIT1()  asm volatile("cp.async.wait_group 1;" ::: "memory")
#define CP_WAIT0()  asm volatile("cp.async.wait_group 0;" ::: "memory")

// ===========================================================================
// conversion kernel: fp32 -> fp16
// ===========================================================================
__global__ void __launch_bounds__(256)
conv_fp16(const float* __restrict__ in, __half* __restrict__ out, int n)
{
    int i = (blockIdx.x * 256 + threadIdx.x) * 4;
    if (i >= n) return;
    float4 v = *(const float4*)(in + i);
    *(uint2*)(out + i) = make_uint2(pack2(f16_of(v.x), f16_of(v.y)),
                                    pack2(f16_of(v.z), f16_of(v.w)));
}

// ===========================================================================
// fp16 GEMM (1 mma pass). CTA 128x128, warp 64x32 (2x4), K-chunk 64,
// cp.async double-buffered pipeline, 2 CTAs/SM (regs capped at 128).
// ===========================================================================
#define A_STRIDE 72          // fp16 elems per A row (144 B; 64 data + 8 pad)
#define B_STRIDE 136         // fp16 elems per B row (272 B)
#define A_PLANE  (128 * A_STRIDE * 2)     // 18432 B
#define B_PLANE  (64 * B_STRIDE * 2)      // 17408 B
#define OFF_A    0
#define OFF_B    (A_PLANE)
#define BUF_BYTES (A_PLANE + B_PLANE)      // 35840
#define SMEM_GEMM_BYTES (2 * BUF_BYTES)    // 71680

template<bool OUT_F16>
__global__ void __launch_bounds__(256, 2)
gemm_f16(const __half* __restrict__ Ah, const __half* __restrict__ Bh,
         const float* __restrict__ bias, float* __restrict__ C,
         __half* __restrict__ C16, int M, int N, int K)
{
    extern __shared__ char smem[];
    const uint32_t sbase = smem_u32(smem);
    const int t    = threadIdx.x;
    const int lane = t & 31;
    const int wid  = t >> 5;
    const int warp_m = wid >> 2;
    const int warp_n = wid & 3;

    const int n0 = blockIdx.x * 128;
    const int m0 = blockIdx.y * 128;

    float acc[4][4][4];
#pragma unroll
    for (int i = 0; i < 4; i++)
#pragma unroll
        for (int j = 0; j < 4; j++)
#pragma unroll
            for (int r = 0; r < 4; r++) acc[i][j][r] = 0.f;

    // cp.async loaders: A 128x64 (row=idx>>3, g=idx&7); B 64x128 (k=idx>>4, ng=idx&15)
    const int a_m0 = t >> 3, a_g = t & 7;
    const int b_k0 = t >> 4, b_ng = t & 15;

    auto issue_chunk = [&](int c) {
        const int k0 = c * 64;
        const uint32_t buf = sbase + (c & 1) * BUF_BYTES;
#pragma unroll
        for (int p = 0; p < 4; p++) {
            int m = a_m0 + p * 32;
            cp16(buf + OFF_A + m * (A_STRIDE * 2) + a_g * 16,
                 Ah + (size_t)(m0 + m) * K + k0 + a_g * 8);
            int k = b_k0 + p * 16;
            cp16(buf + OFF_B + k * (B_STRIDE * 2) + b_ng * 16,
                 Bh + (size_t)(k0 + k) * N + n0 + b_ng * 8);
        }
    };

    const int NCH = K / 64;
    issue_chunk(0);
    CP_COMMIT();

    for (int c = 0; c < NCH; c++) {
        __syncthreads();                // all warps done reading buf[(c+1)&1] (from chunk c-1)
        if (c + 1 < NCH) {
            issue_chunk(c + 1);
            CP_COMMIT();
            CP_WAIT1();                 // chunk c landed
        } else {
            CP_WAIT0();
        }
        __syncthreads();                // publish chunk c to all warps

        const uint32_t buf = sbase + (c & 1) * BUF_BYTES;
#pragma unroll
        for (int kk = 0; kk < 4; kk++) {
            const int a_row = (lane & 15);
            const int a_cb  = (lane >> 4);
            const int b_kr  = kk * 16 + (lane & 15);
            const int b_nc  = (lane & 16) ? 8 : 0;

            uint32_t af[4][4], bf[2][4];
#pragma unroll
            for (int mt = 0; mt < 4; mt++) {
                int row = warp_m * 64 + mt * 16 + a_row;
                uint32_t ad = buf + OFF_A + (row * A_STRIDE + kk * 16 + a_cb * 8) * 2;
                ldm_x4(af[mt][0], af[mt][1], af[mt][2], af[mt][3], ad);
            }
#pragma unroll
            for (int nb = 0; nb < 2; nb++) {
                int ncol = warp_n * 32 + nb * 16 + b_nc;
                uint32_t bd = buf + OFF_B + (b_kr * B_STRIDE + ncol) * 2;
                ldm_x4_t(bf[nb][0], bf[nb][1], bf[nb][2], bf[nb][3], bd);
            }
#pragma unroll
            for (int mt = 0; mt < 4; mt++)
#pragma unroll
                for (int nt = 0; nt < 4; nt++) {
                    int nb = nt >> 1, half = nt & 1;
                    mma_f16(acc[mt][nt][0], acc[mt][nt][1], acc[mt][nt][2], acc[mt][nt][3],
                            af[mt][0], af[mt][1], af[mt][2], af[mt][3],
                            bf[nb][half * 2], bf[nb][half * 2 + 1]);
                }
        }
    }

    const int r_base = m0 + warp_m * 64 + (lane >> 2);
    const int c_base = n0 + warp_n * 32 + 2 * (lane & 3);
#pragma unroll
    for (int mt = 0; mt < 4; mt++) {
#pragma unroll
        for (int nt = 0; nt < 4; nt++) {
            int col = c_base + nt * 8;
            float b0 = bias[col], b1 = bias[col + 1];
            int r0 = r_base + mt * 16;
            float v00 = acc[mt][nt][0] + b0, v01 = acc[mt][nt][1] + b1;
            float v10 = acc[mt][nt][2] + b0, v11 = acc[mt][nt][3] + b1;
            if (OUT_F16) {
                *(uint32_t*)(C16 + (size_t)r0 * N + col)       = pack2(f16_of(v00), f16_of(v01));
                *(uint32_t*)(C16 + (size_t)(r0 + 8) * N + col) = pack2(f16_of(v10), f16_of(v11));
            } else {
                *(float2*)(C + (size_t)r0 * N + col)       = make_float2(v00, v01);
                *(float2*)(C + (size_t)(r0 + 8) * N + col) = make_float2(v10, v11);
            }
        }
    }
}

// ===========================================================================
// fp16 tensor-core windowed flash attention (unchanged — passing)
// ===========================================================================
#define AT_STR 144
#define OFF_K 0
#define OFF_V 18432
#define SMEM_ATT 36864

__global__ void __launch_bounds__(256, 1)
attn_flash(const __half* __restrict__ qkv, __half* __restrict__ oh_g)
{
    extern __shared__ char smem[];
    const uint32_t sb = smem_u32(smem);
    const int qt = blockIdx.x, h = blockIdx.y, b = blockIdx.z;
    const int t = threadIdx.x, lane = t & 31, wid = t >> 5;

#pragma unroll
    for (int p = 0; p < 4; p++) {
        int idx = t + p * 256;
        int row = idx >> 3, g = idx & 7;
        const __half* src = qkv
            + ((size_t)(b * Lq + qt * QT + row) * 3 + 0) * Dq + h * HDq + g * 8;
        uint4 v = *(const uint4*)src;
        uint32_t dst = sb + OFF_K + row * AT_STR + g * 16;
        asm volatile("st.shared.v4.b32 [%0], {%1,%2,%3,%4};" ::
                     "r"(dst), "r"(v.x), "r"(v.y), "r"(v.z), "r"(v.w) : "memory");
    }
    __syncthreads();

    uint32_t qf[4][4];
    {
        int a_row = lane & 15, a_cb = lane >> 4;
        int qrow = wid * 16 + a_row;
#pragma unroll
        for (int ks = 0; ks < 4; ks++) {
            uint32_t ad = sb + OFF_K + qrow * AT_STR + (ks * 16 + a_cb * 8) * 2;
            ldm_x4(qf[ks][0], qf[ks][1], qf[ks][2], qf[ks][3], ad);
        }
    }

    float o[8][4];
#pragma unroll
    for (int i = 0; i < 8; i++)
#pragma unroll
        for (int r = 0; r < 4; r++) o[i][r] = 0.f;
    float ls0 = 0.f, ls1 = 0.f;

    const int i_lo = wid * 16 + (lane >> 2);
    const int i_hi = i_lo + 8;
    const int jj_b = (lane & 3) * 2;

    const int bn_row = (lane & 7) + ((lane & 16) >> 1);
    const int bk_off = (lane & 8);
    const int v_kr = (lane & 15);
    const int v_nc = (lane & 16) ? 8 : 0;

    for (int ch = 0; ch < 3; ch++) {
        if (ch == 0 && qt == 0) continue;
        if (ch == 2 && qt == (Lq / QT) - 1) continue;
        const int jbase = qt * QT + (ch - 1) * 128;

        __syncthreads();
#pragma unroll
        for (int p = 0; p < 8; p++) {
            int idx = t + p * 256;
            int plane = idx >> 10, rem = idx & 1023, row = rem >> 3, g = rem & 7;
            int which = plane + 1;     // 1 = K, 2 = V
            const __half* src = qkv
                + ((size_t)(b * Lq + jbase + row) * 3 + which) * Dq + h * HDq + g * 8;
            uint4 v = *(const uint4*)src;
            uint32_t off = plane ? OFF_V : OFF_K;
            uint32_t dst = sb + off + row * AT_STR + g * 16;
            asm volatile("st.shared.v4.b32 [%0], {%1,%2,%3,%4};" ::
                         "r"(dst), "r"(v.x), "r"(v.y), "r"(v.z), "r"(v.w) : "memory");
        }
        __syncthreads();

        float sacc[16][4];
#pragma unroll
        for (int i = 0; i < 16; i++)
#pragma unroll
            for (int r = 0; r < 4; r++) sacc[i][r] = 0.f;

#pragma unroll
        for (int ks = 0; ks < 4; ks++) {
#pragma unroll
            for (int ng = 0; ng < 8; ng++) {
                uint32_t k0, k1, k2, k3;
                uint32_t ad = sb + OFF_K + (ng * 16 + bn_row) * AT_STR + (ks * 16 + bk_off) * 2;
                ldm_x4(k0, k1, k2, k3, ad);
                int n0 = ng * 2, n1 = ng * 2 + 1;
                mma_f16(sacc[n0][0], sacc[n0][1], sacc[n0][2], sacc[n0][3],
                        qf[ks][0], qf[ks][1], qf[ks][2], qf[ks][3], k0, k1);
                mma_f16(sacc[n1][0], sacc[n1][1], sacc[n1][2], sacc[n1][3],
                        qf[ks][0], qf[ks][1], qf[ks][2], qf[ks][3], k2, k3);
            }
        }

        uint32_t pp[16][2];
#pragma unroll
        for (int nt = 0; nt < 16; nt++) {
            int jj0 = nt * 8 + jj_b, jj1 = jj0 + 1;
            float p0 = __expf(sacc[nt][0] * 0.125f);
            float p1 = __expf(sacc[nt][1] * 0.125f);
            float p2 = __expf(sacc[nt][2] * 0.125f);
            float p3 = __expf(sacc[nt][3] * 0.125f);
            if (ch == 0) {
                if (jj0 < i_lo) p0 = 0.f;
                if (jj1 < i_lo) p1 = 0.f;
                if (jj0 < i_hi) p2 = 0.f;
                if (jj1 < i_hi) p3 = 0.f;
            } else if (ch == 2) {
                if (jj0 > i_lo) p0 = 0.f;
                if (jj1 > i_lo) p1 = 0.f;
                if (jj0 > i_hi) p2 = 0.f;
                if (jj1 > i_hi) p3 = 0.f;
            }
            ls0 += p0 + p1;
            ls1 += p2 + p3;
            pp[nt][0] = f16x2_of(p0, p1);
            pp[nt][1] = f16x2_of(p2, p3);
        }

#pragma unroll
        for (int ks = 0; ks < 8; ks++) {
            uint32_t a0 = pp[2 * ks][0], a1 = pp[2 * ks][1];
            uint32_t a2 = pp[2 * ks + 1][0], a3 = pp[2 * ks + 1][1];
#pragma unroll
            for (int ng = 0; ng < 4; ng++) {
                uint32_t v0, v1, v2, v3;
                uint32_t ad = sb + OFF_V + (ks * 16 + v_kr) * AT_STR + (ng * 16 + v_nc) * 2;
                ldm_x4_t(v0, v1, v2, v3, ad);
                int d0 = ng * 2, d1 = ng * 2 + 1;
                mma_f16(o[d0][0], o[d0][1], o[d0][2], o[d0][3], a0, a1, a2, a3, v0, v1);
                mma_f16(o[d1][0], o[d1][1], o[d1][2], o[d1][3], a0, a1, a2, a3, v2, v3);
            }
        }
    }

    ls0 += __shfl_xor_sync(0xffffffffu, ls0, 1);
    ls0 += __shfl_xor_sync(0xffffffffu, ls0, 2);
    ls1 += __shfl_xor_sync(0xffffffffu, ls1, 1);
    ls1 += __shfl_xor_sync(0xffffffffu, ls1, 2);
    float inv0 = 1.f / ls0, inv1 = 1.f / ls1;

    const int qg0 = qt * QT + i_lo;
#pragma unroll
    for (int dt = 0; dt < 8; dt++) {
        int d = h * HDq + dt * 8 + jj_b;
        size_t base0 = (size_t)(b * Lq + qg0) * Dq + d;
        size_t base1 = base0 + (size_t)8 * Dq;
        *(uint32_t*)(oh_g + base0) = pack2(f16_of(o[dt][0] * inv0), f16_of(o[dt][1] * inv0));
        *(uint32_t*)(oh_g + base1) = pack2(f16_of(o[dt][2] * inv1), f16_of(o[dt][3] * inv1));
    }
}

// ---------------------------------------------------------------------------
extern "C" void kernel_launch(void* const* d_in, const int* in_sizes, int n_in,
                              void* d_out, int out_size)
{
    const float* x     = (const float*)d_in[0];
    const float* w_qkv = (const float*)d_in[1];
    const float* b_qkv = (const float*)d_in[2];
    const float* w_out = (const float*)d_in[3];
    const float* b_out = (const float*)d_in[4];
    float* out = (float*)d_out;

    __half *qkv16, *xh, *wh, *oh, *ah;
    cudaGetSymbolAddress((void**)&qkv16, g_qkv16);
    cudaGetSymbolAddress((void**)&xh, g_x_h);
    cudaGetSymbolAddress((void**)&wh, g_wqkv_h);
    cudaGetSymbolAddress((void**)&oh, g_wout_h);
    cudaGetSymbolAddress((void**)&ah, g_attn_h);

    const int M = Bq * Lq;    // 4096

    cudaFuncSetAttribute(gemm_f16<true>,  cudaFuncAttributeMaxDynamicSharedMemorySize, SMEM_GEMM_BYTES);
    cudaFuncSetAttribute(gemm_f16<false>, cudaFuncAttributeMaxDynamicSharedMemorySize, SMEM_GEMM_BYTES);
    cudaFuncSetAttribute(attn_flash, cudaFuncAttributeMaxDynamicSharedMemorySize, SMEM_ATT);

    // 0) conversions to fp16
    conv_fp16<<<(M * Dq) / 1024, 256>>>(x, xh, M * Dq);
    conv_fp16<<<(Dq * 3 * Dq) / 1024, 256>>>(w_qkv, wh, Dq * 3 * Dq);
    conv_fp16<<<(Dq * Dq) / 1024, 256>>>(w_out, oh, Dq * Dq);

    // 1) QKV projection -> single fp16 plane
    {
        dim3 grid(3 * Dq / 128, M / 128);   // 24 x 32
        gemm_f16<true><<<grid, 256, SMEM_GEMM_BYTES>>>(
            xh, wh, b_qkv, nullptr, qkv16, M, 3 * Dq, Dq);
    }

    // 2) fp16 tensor-core windowed attention
    {
        dim3 grid(Lq / QT, Hq, Bq);
        attn_flash<<<grid, 256, SMEM_ATT>>>(qkv16, ah);
    }

    // 3) Output projection -> fp32 out
    {
        dim3 grid(Dq / 128, M / 128);       // 8 x 32
        gemm_f16<false><<<grid, 256, SMEM_GEMM_BYTES>>>(
            ah, oh, b_out, out, nullptr, M, Dq, Dq);
    }
}

// round 16
// speedup vs baseline: 2.3159x; 1.0002x over previous
#include <cuda_runtime.h>
#include <cuda_fp16.h>
#include <cstdint>
#include <math.h>

#define Bq 2
#define Lq 2048
#define Dq 1024
#define Hq 16
#define HDq 64
#define HALFW 128
#define QT 128

// Scratch (no cudaMalloc allowed)
__device__ __half g_qkv16[(size_t)Bq * Lq * 3 * Dq];  // [B,L,3,D] single fp16
__device__ __half g_x_h[(size_t)Bq * Lq * Dq];
__device__ __half g_wqkv_h[(size_t)Dq * 3 * Dq];
__device__ __half g_wout_h[(size_t)Dq * Dq];
__device__ __half g_attn_h[(size_t)Bq * Lq * Dq];

// ===========================================================================
// helpers
// ===========================================================================
__device__ __forceinline__ uint16_t f16_of(float x) {
    return __half_raw(__float2half_rn(x)).x;
}

__device__ __forceinline__ uint32_t pack2(uint16_t a, uint16_t b) {
    return (uint32_t)a | ((uint32_t)b << 16);
}

__device__ __forceinline__ uint32_t f16x2_of(float flo, float fhi) {
    uint32_t r;
    asm("cvt.rn.f16x2.f32 %0, %1, %2;" : "=r"(r) : "f"(fhi), "f"(flo));
    return r;
}

__device__ __forceinline__ uint32_t smem_u32(const void* p) {
    uint32_t a;
    asm("{ .reg .u64 t; cvta.to.shared.u64 t, %1; cvt.u32.u64 %0, t; }" : "=r"(a) : "l"(p));
    return a;
}

__device__ __forceinline__ void ldm_x4(uint32_t& r0, uint32_t& r1, uint32_t& r2, uint32_t& r3,
                                       uint32_t addr) {
    asm volatile("ldmatrix.sync.aligned.m8n8.x4.shared.b16 {%0,%1,%2,%3}, [%4];"
                 : "=r"(r0), "=r"(r1), "=r"(r2), "=r"(r3) : "r"(addr));
}
__device__ __forceinline__ void ldm_x4_t(uint32_t& r0, uint32_t& r1, uint32_t& r2, uint32_t& r3,
                                         uint32_t addr) {
    asm volatile("ldmatrix.sync.aligned.m8n8.x4.trans.shared.b16 {%0,%1,%2,%3}, [%4];"
                 : "=r"(r0), "=r"(r1), "=r"(r2), "=r"(r3) : "r"(addr));
}

__device__ __forceinline__ void mma_f16(float& d0, float& d1, float& d2, float& d3,
                                        uint32_t a0, uint32_t a1, uint32_t a2, uint32_t a3,
                                        uint32_t b0, uint32_t b1) {
    asm volatile(
        "mma.sync.aligned.m16n8k16.row.col.f32.f16.f16.f32 "
        "{%0,%1,%2,%3}, {%4,%5,%6,%7}, {%8,%9}, {%0,%1,%2,%3};"
        : "+f"(d0), "+f"(d1), "+f"(d2), "+f"(d3)
        : "r"(a0), "r"(a1), "r"(a2), "r"(a3), "r"(b0), "r"(b1));
}

__device__ __forceinline__ void cp16(uint32_t s, const void* g) {
    asm volatile("cp.async.cg.shared.global [%0], [%1], 16;" :: "r"(s), "l"(g) : "memory");
}
#define CP_COMMIT() asm volatile("cp.async.commit_group;" ::: "memory")
#define CP_WAIT0()  asm volatile("cp.async.wait_group 0;" ::: "memory")

// ===========================================================================
// conversion kernel: fp32 -> fp16
// ===========================================================================
__global__ void __launch_bounds__(256)
conv_fp16(const float* __restrict__ in, __half* __restrict__ out, int n)
{
    int i = (blockIdx.x * 256 + threadIdx.x) * 4;
    if (i >= n) return;
    float4 v = *(const float4*)(in + i);
    *(uint2*)(out + i) = make_uint2(pack2(f16_of(v.x), f16_of(v.y)),
                                    pack2(f16_of(v.z), f16_of(v.w)));
}

// ===========================================================================
// fp16 GEMM (1 mma pass). CTA 128x128, warp 64x32 (2x4), K-chunk 64,
// cp.async double-buffered pipeline (ONE barrier per chunk), 2 CTAs/SM.
// ===========================================================================
#define A_STRIDE 72          // fp16 elems per A row (144 B; 64 data + 8 pad)
#define B_STRIDE 136         // fp16 elems per B row (272 B)
#define A_PLANE  (128 * A_STRIDE * 2)     // 18432 B
#define B_PLANE  (64 * B_STRIDE * 2)      // 17408 B
#define OFF_A    0
#define OFF_B    (A_PLANE)
#define BUF_BYTES (A_PLANE + B_PLANE)      // 35840
#define SMEM_GEMM_BYTES (2 * BUF_BYTES)    // 71680

template<bool OUT_F16>
__global__ void __launch_bounds__(256, 2)
gemm_f16(const __half* __restrict__ Ah, const __half* __restrict__ Bh,
         const float* __restrict__ bias, float* __restrict__ C,
         __half* __restrict__ C16, int M, int N, int K)
{
    extern __shared__ char smem[];
    const uint32_t sbase = smem_u32(smem);
    const int t    = threadIdx.x;
    const int lane = t & 31;
    const int wid  = t >> 5;
    const int warp_m = wid >> 2;
    const int warp_n = wid & 3;

    const int n0 = blockIdx.x * 128;
    const int m0 = blockIdx.y * 128;

    float acc[4][4][4];
#pragma unroll
    for (int i = 0; i < 4; i++)
#pragma unroll
        for (int j = 0; j < 4; j++)
#pragma unroll
            for (int r = 0; r < 4; r++) acc[i][j][r] = 0.f;

    const int a_m0 = t >> 3, a_g = t & 7;
    const int b_k0 = t >> 4, b_ng = t & 15;

    auto issue_chunk = [&](int c) {
        const int k0 = c * 64;
        const uint32_t buf = sbase + (c & 1) * BUF_BYTES;
#pragma unroll
        for (int p = 0; p < 4; p++) {
            int m = a_m0 + p * 32;
            cp16(buf + OFF_A + m * (A_STRIDE * 2) + a_g * 16,
                 Ah + (size_t)(m0 + m) * K + k0 + a_g * 8);
            int k = b_k0 + p * 16;
            cp16(buf + OFF_B + k * (B_STRIDE * 2) + b_ng * 16,
                 Bh + (size_t)(k0 + k) * N + n0 + b_ng * 8);
        }
    };

    const int NCH = K / 64;
    issue_chunk(0);
    CP_COMMIT();

    for (int c = 0; c < NCH; c++) {
        CP_WAIT0();                 // chunk c landed (had all of compute(c-1) to arrive)
        __syncthreads();            // publish chunk c; prove compute(c-1) complete (WAR-safe)
        if (c + 1 < NCH) {
            issue_chunk(c + 1);     // into buf last read at iter c-1
            CP_COMMIT();
        }

        const uint32_t buf = sbase + (c & 1) * BUF_BYTES;
#pragma unroll
        for (int kk = 0; kk < 4; kk++) {
            const int a_row = (lane & 15);
            const int a_cb  = (lane >> 4);
            const int b_kr  = kk * 16 + (lane & 15);
            const int b_nc  = (lane & 16) ? 8 : 0;

            uint32_t af[4][4], bf[2][4];
#pragma unroll
            for (int mt = 0; mt < 4; mt++) {
                int row = warp_m * 64 + mt * 16 + a_row;
                uint32_t ad = buf + OFF_A + (row * A_STRIDE + kk * 16 + a_cb * 8) * 2;
                ldm_x4(af[mt][0], af[mt][1], af[mt][2], af[mt][3], ad);
            }
#pragma unroll
            for (int nb = 0; nb < 2; nb++) {
                int ncol = warp_n * 32 + nb * 16 + b_nc;
                uint32_t bd = buf + OFF_B + (b_kr * B_STRIDE + ncol) * 2;
                ldm_x4_t(bf[nb][0], bf[nb][1], bf[nb][2], bf[nb][3], bd);
            }
#pragma unroll
            for (int mt = 0; mt < 4; mt++)
#pragma unroll
                for (int nt = 0; nt < 4; nt++) {
                    int nb = nt >> 1, half = nt & 1;
                    mma_f16(acc[mt][nt][0], acc[mt][nt][1], acc[mt][nt][2], acc[mt][nt][3],
                            af[mt][0], af[mt][1], af[mt][2], af[mt][3],
                            bf[nb][half * 2], bf[nb][half * 2 + 1]);
                }
        }
    }

    const int r_base = m0 + warp_m * 64 + (lane >> 2);
    const int c_base = n0 + warp_n * 32 + 2 * (lane & 3);
#pragma unroll
    for (int mt = 0; mt < 4; mt++) {
#pragma unroll
        for (int nt = 0; nt < 4; nt++) {
            int col = c_base + nt * 8;
            float b0 = bias[col], b1 = bias[col + 1];
            int r0 = r_base + mt * 16;
            float v00 = acc[mt][nt][0] + b0, v01 = acc[mt][nt][1] + b1;
            float v10 = acc[mt][nt][2] + b0, v11 = acc[mt][nt][3] + b1;
            if (OUT_F16) {
                *(uint32_t*)(C16 + (size_t)r0 * N + col)       = pack2(f16_of(v00), f16_of(v01));
                *(uint32_t*)(C16 + (size_t)(r0 + 8) * N + col) = pack2(f16_of(v10), f16_of(v11));
            } else {
                *(float2*)(C + (size_t)r0 * N + col)       = make_float2(v00, v01);
                *(float2*)(C + (size_t)(r0 + 8) * N + col) = make_float2(v10, v11);
            }
        }
    }
}

// ===========================================================================
// fp16 tensor-core windowed flash attention with triangular block-skip.
// Chunk 0 (mask jj>=i): key blocks ng < wid are entirely masked -> skipped.
// Chunk 2 (mask jj<=i): key blocks ng > wid entirely masked -> skipped.
// Skipped blocks previously contributed exact zeros, so output is bit-identical.
// ===========================================================================
#define AT_STR 144
#define OFF_K 0
#define OFF_V 18432
#define SMEM_ATT 36864

__global__ void __launch_bounds__(256, 1)
attn_flash(const __half* __restrict__ qkv, __half* __restrict__ oh_g)
{
    extern __shared__ char smem[];
    const uint32_t sb = smem_u32(smem);
    const int qt = blockIdx.x, h = blockIdx.y, b = blockIdx.z;
    const int t = threadIdx.x, lane = t & 31, wid = t >> 5;

#pragma unroll
    for (int p = 0; p < 4; p++) {
        int idx = t + p * 256;
        int row = idx >> 3, g = idx & 7;
        const __half* src = qkv
            + ((size_t)(b * Lq + qt * QT + row) * 3 + 0) * Dq + h * HDq + g * 8;
        uint4 v = *(const uint4*)src;
        uint32_t dst = sb + OFF_K + row * AT_STR + g * 16;
        asm volatile("st.shared.v4.b32 [%0], {%1,%2,%3,%4};" ::
                     "r"(dst), "r"(v.x), "r"(v.y), "r"(v.z), "r"(v.w) : "memory");
    }
    __syncthreads();

    uint32_t qf[4][4];
    {
        int a_row = lane & 15, a_cb = lane >> 4;
        int qrow = wid * 16 + a_row;
#pragma unroll
        for (int ks = 0; ks < 4; ks++) {
            uint32_t ad = sb + OFF_K + qrow * AT_STR + (ks * 16 + a_cb * 8) * 2;
            ldm_x4(qf[ks][0], qf[ks][1], qf[ks][2], qf[ks][3], ad);
        }
    }

    float o[8][4];
#pragma unroll
    for (int i = 0; i < 8; i++)
#pragma unroll
        for (int r = 0; r < 4; r++) o[i][r] = 0.f;
    float ls0 = 0.f, ls1 = 0.f;

    const int i_lo = wid * 16 + (lane >> 2);
    const int i_hi = i_lo + 8;
    const int jj_b = (lane & 3) * 2;

    const int bn_row = (lane & 7) + ((lane & 16) >> 1);
    const int bk_off = (lane & 8);
    const int v_kr = (lane & 15);
    const int v_nc = (lane & 16) ? 8 : 0;

    for (int ch = 0; ch < 3; ch++) {
        if (ch == 0 && qt == 0) continue;
        if (ch == 2 && qt == (Lq / QT) - 1) continue;
        const int jbase = qt * QT + (ch - 1) * 128;

        __syncthreads();
#pragma unroll
        for (int p = 0; p < 8; p++) {
            int idx = t + p * 256;
            int plane = idx >> 10, rem = idx & 1023, row = rem >> 3, g = rem & 7;
            int which = plane + 1;     // 1 = K, 2 = V
            const __half* src = qkv
                + ((size_t)(b * Lq + jbase + row) * 3 + which) * Dq + h * HDq + g * 8;
            uint4 v = *(const uint4*)src;
            uint32_t off = plane ? OFF_V : OFF_K;
            uint32_t dst = sb + off + row * AT_STR + g * 16;
            asm volatile("st.shared.v4.b32 [%0], {%1,%2,%3,%4};" ::
                         "r"(dst), "r"(v.x), "r"(v.y), "r"(v.z), "r"(v.w) : "memory");
        }
        __syncthreads();

        // ---- S = Q K^T (skip fully-masked key blocks) ----
        float sacc[16][4];
#pragma unroll
        for (int i = 0; i < 16; i++)
#pragma unroll
            for (int r = 0; r < 4; r++) sacc[i][r] = 0.f;

#pragma unroll
        for (int ng = 0; ng < 8; ng++) {
            if (ch == 0 && ng < wid) continue;     // keys entirely below window
            if (ch == 2 && ng > wid) continue;     // keys entirely above window
#pragma unroll
            for (int ks = 0; ks < 4; ks++) {
                uint32_t k0, k1, k2, k3;
                uint32_t ad = sb + OFF_K + (ng * 16 + bn_row) * AT_STR + (ks * 16 + bk_off) * 2;
                ldm_x4(k0, k1, k2, k3, ad);
                int n0 = ng * 2, n1 = ng * 2 + 1;
                mma_f16(sacc[n0][0], sacc[n0][1], sacc[n0][2], sacc[n0][3],
                        qf[ks][0], qf[ks][1], qf[ks][2], qf[ks][3], k0, k1);
                mma_f16(sacc[n1][0], sacc[n1][1], sacc[n1][2], sacc[n1][3],
                        qf[ks][0], qf[ks][1], qf[ks][2], qf[ks][3], k2, k3);
            }
        }

        // ---- mask + exp + row-sum + pack P (skip fully-masked 8-key blocks) ----
        uint32_t pp[16][2];
#pragma unroll
        for (int nt = 0; nt < 16; nt++) {
            if (ch == 0 && nt < 2 * wid) continue;
            if (ch == 2 && nt >= 2 * wid + 2) continue;
            int jj0 = nt * 8 + jj_b, jj1 = jj0 + 1;
            float p0 = __expf(sacc[nt][0] * 0.125f);
            float p1 = __expf(sacc[nt][1] * 0.125f);
            float p2 = __expf(sacc[nt][2] * 0.125f);
            float p3 = __expf(sacc[nt][3] * 0.125f);
            if (ch == 0) {
                if (jj0 < i_lo) p0 = 0.f;
                if (jj1 < i_lo) p1 = 0.f;
                if (jj0 < i_hi) p2 = 0.f;
                if (jj1 < i_hi) p3 = 0.f;
            } else if (ch == 2) {
                if (jj0 > i_lo) p0 = 0.f;
                if (jj1 > i_lo) p1 = 0.f;
                if (jj0 > i_hi) p2 = 0.f;
                if (jj1 > i_hi) p3 = 0.f;
            }
            ls0 += p0 + p1;
            ls1 += p2 + p3;
            pp[nt][0] = f16x2_of(p0, p1);
            pp[nt][1] = f16x2_of(p2, p3);
        }

        // ---- O += P V (skip fully-masked 16-key blocks) ----
#pragma unroll
        for (int ks = 0; ks < 8; ks++) {
            if (ch == 0 && ks < wid) continue;
            if (ch == 2 && ks > wid) continue;
            uint32_t a0 = pp[2 * ks][0], a1 = pp[2 * ks][1];
            uint32_t a2 = pp[2 * ks + 1][0], a3 = pp[2 * ks + 1][1];
#pragma unroll
            for (int ng = 0; ng < 4; ng++) {
                uint32_t v0, v1, v2, v3;
                uint32_t ad = sb + OFF_V + (ks * 16 + v_kr) * AT_STR + (ng * 16 + v_nc) * 2;
                ldm_x4_t(v0, v1, v2, v3, ad);
                int d0 = ng * 2, d1 = ng * 2 + 1;
                mma_f16(o[d0][0], o[d0][1], o[d0][2], o[d0][3], a0, a1, a2, a3, v0, v1);
                mma_f16(o[d1][0], o[d1][1], o[d1][2], o[d1][3], a0, a1, a2, a3, v2, v3);
            }
        }
    }

    ls0 += __shfl_xor_sync(0xffffffffu, ls0, 1);
    ls0 += __shfl_xor_sync(0xffffffffu, ls0, 2);
    ls1 += __shfl_xor_sync(0xffffffffu, ls1, 1);
    ls1 += __shfl_xor_sync(0xffffffffu, ls1, 2);
    float inv0 = 1.f / ls0, inv1 = 1.f / ls1;

    const int qg0 = qt * QT + i_lo;
#pragma unroll
    for (int dt = 0; dt < 8; dt++) {
        int d = h * HDq + dt * 8 + jj_b;
        size_t base0 = (size_t)(b * Lq + qg0) * Dq + d;
        size_t base1 = base0 + (size_t)8 * Dq;
        *(uint32_t*)(oh_g + base0) = pack2(f16_of(o[dt][0] * inv0), f16_of(o[dt][1] * inv0));
        *(uint32_t*)(oh_g + base1) = pack2(f16_of(o[dt][2] * inv1), f16_of(o[dt][3] * inv1));
    }
}

// ---------------------------------------------------------------------------
extern "C" void kernel_launch(void* const* d_in, const int* in_sizes, int n_in,
                              void* d_out, int out_size)
{
    const float* x     = (const float*)d_in[0];
    const float* w_qkv = (const float*)d_in[1];
    const float* b_qkv = (const float*)d_in[2];
    const float* w_out = (const float*)d_in[3];
    const float* b_out = (const float*)d_in[4];
    float* out = (float*)d_out;

    __half *qkv16, *xh, *wh, *oh, *ah;
    cudaGetSymbolAddress((void**)&qkv16, g_qkv16);
    cudaGetSymbolAddress((void**)&xh, g_x_h);
    cudaGetSymbolAddress((void**)&wh, g_wqkv_h);
    cudaGetSymbolAddress((void**)&oh, g_wout_h);
    cudaGetSymbolAddress((void**)&ah, g_attn_h);

    const int M = Bq * Lq;    // 4096

    cudaFuncSetAttribute(gemm_f16<true>,  cudaFuncAttributeMaxDynamicSharedMemorySize, SMEM_GEMM_BYTES);
    cudaFuncSetAttribute(gemm_f16<false>, cudaFuncAttributeMaxDynamicSharedMemorySize, SMEM_GEMM_BYTES);
    cudaFuncSetAttribute(attn_flash, cudaFuncAttributeMaxDynamicSharedMemorySize, SMEM_ATT);

    // 0) conversions to fp16
    conv_fp16<<<(M * Dq) / 1024, 256>>>(x, xh, M * Dq);
    conv_fp16<<<(Dq * 3 * Dq) / 1024, 256>>>(w_qkv, wh, Dq * 3 * Dq);
    conv_fp16<<<(Dq * Dq) / 1024, 256>>>(w_out, oh, Dq * Dq);

    // 1) QKV projection -> single fp16 plane
    {
        dim3 grid(3 * Dq / 128, M / 128);   // 24 x 32
        gemm_f16<true><<<grid, 256, SMEM_GEMM_BYTES>>>(
            xh, wh, b_qkv, nullptr, qkv16, M, 3 * Dq, Dq);
    }

    // 2) fp16 tensor-core windowed attention
    {
        dim3 grid(Lq / QT, Hq, Bq);
        attn_flash<<<grid, 256, SMEM_ATT>>>(qkv16, ah);
    }

    // 3) Output projection -> fp32 out
    {
        dim3 grid(Dq / 128, M / 128);       // 8 x 32
        gemm_f16<false><<<grid, 256, SMEM_GEMM_BYTES>>>(
            ah, oh, b_out, out, nullptr, M, Dq, Dq);
    }
}